// round 2
// baseline (speedup 1.0000x reference)
#include <cuda_runtime.h>
#include <math.h>

// ---------------- problem constants ----------------
#define Bb   8
#define Tt   12
#define Vv   512
#define Cc   128
#define dd8  8
#define TSZ  3
#define LL   3
#define PP   12
#define BETA 2
#define TPAD (Tt + BETA)   // 14
#define C2   256
#define KV   (TSZ * Vv)    // 1536
#define KTC  (Tt * Cc)     // 1536
#define BT   (Bb * Tt)     // 96

// ---------------- device scratch (static; no runtime alloc) ----------------
__device__ float g_hpad[Bb * TPAD * Vv * Cc];          // 7.34M
__device__ float g_E[LL * Vv * KV];                    // 2.36M
__device__ float g_agg[BT * Vv * Cc];                  // 6.29M
__device__ float g_z[BT * Vv * C2];                    // 12.58M
__device__ float g_s[Bb * Vv * Cc];                    // 0.52M
__device__ float g_skip[Bb * 4 * Cc * Vv];             // 2.10M
__device__ float g_g[Bb * 1024 * Vv];                  // 4.19M
__device__ float g_sep[LL * Vv * C2];                  // 0.39M
__device__ float g_tep[LL * BT * C2];                  // 0.07M
__device__ float g_ascal[LL * BT];
__device__ float g_wk[LL * BT * TSZ];
__device__ float g_fwT[4 * KTC * Cc];                  // 0.79M

__device__ __forceinline__ float sigm(float x) { return 1.f / (1.f + expf(-x)); }

// ---------------- h_pad = [zeros(BETA) ; x@input_w + input_b] ----------------
__global__ void k_input(const float* __restrict__ x, const float* __restrict__ iw,
                        const float* __restrict__ ib) {
    int idx = blockIdx.x * blockDim.x + threadIdx.x;
    if (idx >= Bb * TPAD * Vv * Cc) return;
    int c = idx & 127;
    int rest = idx >> 7;
    int v = rest & 511;
    int bt = rest >> 9;            // b*14 + tp
    int tp = bt % TPAD;
    int b  = bt / TPAD;
    float val = 0.f;
    if (tp >= BETA) {
        float xv = x[(b * Tt + (tp - BETA)) * Vv + v];   // D == 1
        val = xv * iw[c] + ib[c];
    }
    g_hpad[idx] = val;
}

// ---------------- transpose GFS fc weights: fwT[s][t*C+c][o] ----------------
__global__ void k_fwT(const float* __restrict__ fs0, const float* __restrict__ fsl) {
    int idx = blockIdx.x * blockDim.x + threadIdx.x;
    if (idx >= 4 * Cc * KTC) return;
    int tc = idx % KTC;
    int so = idx / KTC;
    int o = so % Cc;
    int s = so / Cc;
    float v = (s == 0) ? fs0[o * KTC + tc] : fsl[((s - 1) * Cc + o) * KTC + tc];
    g_fwT[(s * KTC + tc) * Cc + o] = v;
}

// ---------------- E[l][j][k*V+i] = mask * exp(gi+gj+ge+gtr) ----------------
__global__ void k_buildE(const float* __restrict__ sape, const float* __restrict__ srpe,
                         const float* __restrict__ trpe, const float* __restrict__ mask,
                         const float* __restrict__ mus, const float* __restrict__ isgs) {
    int blk = blockIdx.x;                  // l*V*3 + j*3 + k
    int l = blk / (Vv * 3);
    int rem = blk % (Vv * 3);
    int j = rem / 3, k = rem % 3;
    int i = threadIdx.x;
    __shared__ float mu[48], is[48];
    if (threadIdx.x < 48) { mu[threadIdx.x] = mus[l * 48 + threadIdx.x];
                            is[threadIdx.x] = isgs[l * 48 + threadIdx.x]; }
    __syncthreads();
    float gi = 0.f, gj = 0.f, ge = 0.f, gtr = 0.f;
#pragma unroll
    for (int q = 0; q < 8; q++) {
        float df;
        df = sape[i * 8 + q] - mu[q];        gi  += -0.5f * df * df * is[q] * is[q];
        df = sape[j * 8 + q] - mu[8 + q];    gj  += -0.5f * df * df * is[8 + q] * is[8 + q];
        df = srpe[((size_t)i * Vv + j) * 8 + q] - mu[32 + q];
                                             ge  += -0.5f * df * df * is[32 + q] * is[32 + q];
        df = trpe[k * 8 + q] - mu[40 + q];   gtr += -0.5f * df * df * is[40 + q] * is[40 + q];
    }
    float m = mask[j * KV + k * Vv + i];
    g_E[((size_t)l * Vv + j) * KV + k * Vv + i] = m * expf(gi + gj + ge + gtr);
}

// ---------------- per-(l,b,t) scalars: ascal = exp(gti), wk = exp(gtj) ----------------
__global__ void k_scalars(const float* __restrict__ tape, const float* __restrict__ mus,
                          const float* __restrict__ isgs) {
    int idx = blockIdx.x * blockDim.x + threadIdx.x;
    if (idx >= LL * BT) return;
    int l = idx / BT, bt = idx % BT;
    int b = bt / Tt, t = bt % Tt;
    const float* mu2 = mus + (l * 6 + 2) * 8; const float* is2 = isgs + (l * 6 + 2) * 8;
    const float* mu3 = mus + (l * 6 + 3) * 8; const float* is3 = isgs + (l * 6 + 3) * 8;
    float gti = 0.f;
    const float* tp = tape + (b * Tt + t) * 8;
#pragma unroll
    for (int q = 0; q < 8; q++) { float df = tp[q] - mu2[q]; gti += -0.5f * df * df * is2[q] * is2[q]; }
    g_ascal[idx] = expf(gti);
    for (int k = 0; k < 3; k++) {
        int s = t + k;
        float gtj = 0.f;
#pragma unroll
        for (int q = 0; q < 8; q++) {
            float e = (s < BETA) ? 0.f : tape[(b * Tt + (s - BETA)) * 8 + q];
            float df = e - mu3[q];
            gtj += -0.5f * df * df * is3[q] * is3[q];
        }
        g_wk[idx * 3 + k] = expf(gtj);
    }
}

// ---------------- SEP[v][c2] and TEP[b,t][c2] (TEP includes xproj_b) ----------------
__global__ void k_septep(const float* __restrict__ sape, const float* __restrict__ tape,
                         const float* __restrict__ sew, const float* __restrict__ tew,
                         const float* __restrict__ xpb) {
    int idx = blockIdx.x * blockDim.x + threadIdx.x;
    const int NSEP = LL * Vv * C2;
    const int NTEP = LL * BT * C2;
    if (idx < NSEP) {
        int l = idx / (Vv * C2);
        int v = (idx / C2) % Vv;
        int c2 = idx % C2;
        float acc = 0.f;
#pragma unroll
        for (int q = 0; q < 8; q++) acc += sape[v * 8 + q] * sew[(l * 8 + q) * C2 + c2];
        g_sep[idx] = acc;
    } else if (idx < NSEP + NTEP) {
        int jdx = idx - NSEP;
        int l = jdx / (BT * C2);
        int bt = (jdx / C2) % BT;
        int c2 = jdx % C2;
        float acc = xpb[l * C2 + c2];
#pragma unroll
        for (int q = 0; q < 8; q++) acc += tape[bt * 8 + q] * tew[(l * 8 + q) * C2 + c2];
        g_tep[jdx] = acc;
    }
}

// ============ GEMM skeleton: 64x128 tile, 256 threads, K-step 16 ============
// thread (ty,tx) in 16x16 grid computes 4 rows x 8 cols.

// ---- main aggregation: agg[bt][j][c] = ascal * sum_kv E[j,kv]*wk[k]*hpad[b,t+k,i,c]
__global__ __launch_bounds__(256) void k_agg(int l) {
    __shared__ float As[16][65];
    __shared__ float Bs[16][132];
    int bt = blockIdx.y, b = bt / Tt, t = bt % Tt;
    int j0 = blockIdx.x * 64;
    const float* Abase = g_E + ((size_t)l * Vv + j0) * KV;
    float wk0 = g_wk[(l * BT + bt) * 3 + 0];
    float wk1 = g_wk[(l * BT + bt) * 3 + 1];
    float wk2 = g_wk[(l * BT + bt) * 3 + 2];
    float ascal = g_ascal[l * BT + bt];
    int tid = threadIdx.x;
    int arow = tid >> 2, acol = (tid & 3) << 2;
    int brow = tid >> 4, bcol = (tid & 15) << 3;
    int ty = tid >> 4, tx = tid & 15;
    float acc[4][8];
#pragma unroll
    for (int r = 0; r < 4; r++)
#pragma unroll
        for (int c = 0; c < 8; c++) acc[r][c] = 0.f;
    const float* hb = g_hpad + (size_t)b * TPAD * Vv * Cc;
    for (int kv0 = 0; kv0 < KV; kv0 += 16) {
        float4 av = *(const float4*)(Abase + (size_t)arow * KV + kv0 + acol);
        float w = (kv0 < 512) ? wk0 : (kv0 < 1024 ? wk1 : wk2);
        As[acol + 0][arow] = av.x * w;
        As[acol + 1][arow] = av.y * w;
        As[acol + 2][arow] = av.z * w;
        As[acol + 3][arow] = av.w * w;
        int kv = kv0 + brow;
        int k = kv >> 9, i = kv & 511;
        const float* bp = hb + ((size_t)(t + k) * Vv + i) * Cc + bcol;
        *(float4*)&Bs[brow][bcol]     = *(const float4*)bp;
        *(float4*)&Bs[brow][bcol + 4] = *(const float4*)(bp + 4);
        __syncthreads();
#pragma unroll
        for (int kk = 0; kk < 16; kk++) {
            float a0 = As[kk][ty * 4 + 0], a1 = As[kk][ty * 4 + 1];
            float a2 = As[kk][ty * 4 + 2], a3 = As[kk][ty * 4 + 3];
            float bb[8];
            *(float4*)bb       = *(const float4*)&Bs[kk][tx * 8];
            *(float4*)(bb + 4) = *(const float4*)&Bs[kk][tx * 8 + 4];
#pragma unroll
            for (int c = 0; c < 8; c++) {
                acc[0][c] += a0 * bb[c]; acc[1][c] += a1 * bb[c];
                acc[2][c] += a2 * bb[c]; acc[3][c] += a3 * bb[c];
            }
        }
        __syncthreads();
    }
    float* op = g_agg + ((size_t)bt * Vv + j0) * Cc;
#pragma unroll
    for (int r = 0; r < 4; r++) {
        float4* dst = (float4*)(op + (size_t)(ty * 4 + r) * Cc + tx * 8);
        dst[0] = make_float4(acc[r][0] * ascal, acc[r][1] * ascal, acc[r][2] * ascal, acc[r][3] * ascal);
        dst[1] = make_float4(acc[r][4] * ascal, acc[r][5] * ascal, acc[r][6] * ascal, acc[r][7] * ascal);
    }
}

// ---- z = agg @ xproj_w[l] : M=BT*V, K=128, N=256
__global__ __launch_bounds__(256) void k_zgemm(const float* __restrict__ xw) {
    __shared__ float As[16][65];
    __shared__ float Bs[16][132];
    int m0 = blockIdx.x * 64;
    int n0 = blockIdx.y * 128;
    int tid = threadIdx.x;
    int arow = tid >> 2, acol = (tid & 3) << 2;
    int brow = tid >> 4, bcol = (tid & 15) << 3;
    int ty = tid >> 4, tx = tid & 15;
    float acc[4][8];
#pragma unroll
    for (int r = 0; r < 4; r++)
#pragma unroll
        for (int c = 0; c < 8; c++) acc[r][c] = 0.f;
    for (int kv0 = 0; kv0 < Cc; kv0 += 16) {
        float4 av = *(const float4*)(g_agg + (size_t)(m0 + arow) * Cc + kv0 + acol);
        As[acol + 0][arow] = av.x; As[acol + 1][arow] = av.y;
        As[acol + 2][arow] = av.z; As[acol + 3][arow] = av.w;
        const float* bp = xw + (size_t)(kv0 + brow) * C2 + n0 + bcol;
        *(float4*)&Bs[brow][bcol]     = *(const float4*)bp;
        *(float4*)&Bs[brow][bcol + 4] = *(const float4*)(bp + 4);
        __syncthreads();
#pragma unroll
        for (int kk = 0; kk < 16; kk++) {
            float a0 = As[kk][ty * 4 + 0], a1 = As[kk][ty * 4 + 1];
            float a2 = As[kk][ty * 4 + 2], a3 = As[kk][ty * 4 + 3];
            float bb[8];
            *(float4*)bb       = *(const float4*)&Bs[kk][tx * 8];
            *(float4*)(bb + 4) = *(const float4*)&Bs[kk][tx * 8 + 4];
#pragma unroll
            for (int c = 0; c < 8; c++) {
                acc[0][c] += a0 * bb[c]; acc[1][c] += a1 * bb[c];
                acc[2][c] += a2 * bb[c]; acc[3][c] += a3 * bb[c];
            }
        }
        __syncthreads();
    }
#pragma unroll
    for (int r = 0; r < 4; r++) {
        float4* dst = (float4*)(g_z + (size_t)(m0 + ty * 4 + r) * C2 + n0 + tx * 8);
        dst[0] = make_float4(acc[r][0], acc[r][1], acc[r][2], acc[r][3]);
        dst[1] = make_float4(acc[r][4], acc[r][5], acc[r][6], acc[r][7]);
    }
}

// ---- GFS fc: s[b][v][o] = fb[o] + sum_{t,c} hpad[b,2+t,v,c]*fwT[tc][o]
__global__ __launch_bounds__(256) void k_gfs_s(int sidx, const float* __restrict__ fb) {
    __shared__ float As[16][65];
    __shared__ float Bs[16][132];
    int v0 = blockIdx.x * 64;
    int b = blockIdx.y;
    const float* fwT = g_fwT + (size_t)sidx * KTC * Cc;
    int tid = threadIdx.x;
    int arow = tid >> 2, acol = (tid & 3) << 2;
    int brow = tid >> 4, bcol = (tid & 15) << 3;
    int ty = tid >> 4, tx = tid & 15;
    float acc[4][8];
#pragma unroll
    for (int r = 0; r < 4; r++)
#pragma unroll
        for (int c = 0; c < 8; c++) acc[r][c] = 0.f;
    for (int kv0 = 0; kv0 < KTC; kv0 += 16) {
        int t = kv0 >> 7;
        int cbase = (kv0 & 127) + acol;
        float4 av = *(const float4*)(g_hpad +
            (((size_t)b * TPAD + BETA + t) * Vv + v0 + arow) * Cc + cbase);
        As[acol + 0][arow] = av.x; As[acol + 1][arow] = av.y;
        As[acol + 2][arow] = av.z; As[acol + 3][arow] = av.w;
        const float* bp = fwT + (size_t)(kv0 + brow) * Cc + bcol;
        *(float4*)&Bs[brow][bcol]     = *(const float4*)bp;
        *(float4*)&Bs[brow][bcol + 4] = *(const float4*)(bp + 4);
        __syncthreads();
#pragma unroll
        for (int kk = 0; kk < 16; kk++) {
            float a0 = As[kk][ty * 4 + 0], a1 = As[kk][ty * 4 + 1];
            float a2 = As[kk][ty * 4 + 2], a3 = As[kk][ty * 4 + 3];
            float bb[8];
            *(float4*)bb       = *(const float4*)&Bs[kk][tx * 8];
            *(float4*)(bb + 4) = *(const float4*)&Bs[kk][tx * 8 + 4];
#pragma unroll
            for (int c = 0; c < 8; c++) {
                acc[0][c] += a0 * bb[c]; acc[1][c] += a1 * bb[c];
                acc[2][c] += a2 * bb[c]; acc[3][c] += a3 * bb[c];
            }
        }
        __syncthreads();
    }
#pragma unroll
    for (int r = 0; r < 4; r++) {
        float* dst = g_s + ((size_t)b * Vv + v0 + ty * 4 + r) * Cc + tx * 8;
#pragma unroll
        for (int c = 0; c < 8; c++) dst[c] = acc[r][c] + fb[tx * 8 + c];
    }
}

// ---- head GEMM: g[b][p][v] = glu_b[p] + sum_o glu_w[p,o]*skip[b][o][v]
__global__ __launch_bounds__(256) void k_headg(const float* __restrict__ gw,
                                               const float* __restrict__ gb) {
    __shared__ float As[16][65];
    __shared__ float Bs[16][132];
    int p0 = blockIdx.x * 64;
    int b = blockIdx.y >> 2;
    int n0 = (blockIdx.y & 3) * 128;
    int tid = threadIdx.x;
    int arow = tid >> 2, acol = (tid & 3) << 2;
    int brow = tid >> 4, bcol = (tid & 15) << 3;
    int ty = tid >> 4, tx = tid & 15;
    float acc[4][8];
#pragma unroll
    for (int r = 0; r < 4; r++)
#pragma unroll
        for (int c = 0; c < 8; c++) acc[r][c] = 0.f;
    const float* sk = g_skip + (size_t)b * 512 * Vv;
    for (int kv0 = 0; kv0 < 512; kv0 += 16) {
        float4 av = *(const float4*)(gw + (size_t)(p0 + arow) * 512 + kv0 + acol);
        As[acol + 0][arow] = av.x; As[acol + 1][arow] = av.y;
        As[acol + 2][arow] = av.z; As[acol + 3][arow] = av.w;
        const float* bp = sk + (size_t)(kv0 + brow) * Vv + n0 + bcol;
        *(float4*)&Bs[brow][bcol]     = *(const float4*)bp;
        *(float4*)&Bs[brow][bcol + 4] = *(const float4*)(bp + 4);
        __syncthreads();
#pragma unroll
        for (int kk = 0; kk < 16; kk++) {
            float a0 = As[kk][ty * 4 + 0], a1 = As[kk][ty * 4 + 1];
            float a2 = As[kk][ty * 4 + 2], a3 = As[kk][ty * 4 + 3];
            float bb[8];
            *(float4*)bb       = *(const float4*)&Bs[kk][tx * 8];
            *(float4*)(bb + 4) = *(const float4*)&Bs[kk][tx * 8 + 4];
#pragma unroll
            for (int c = 0; c < 8; c++) {
                acc[0][c] += a0 * bb[c]; acc[1][c] += a1 * bb[c];
                acc[2][c] += a2 * bb[c]; acc[3][c] += a3 * bb[c];
            }
        }
        __syncthreads();
    }
#pragma unroll
    for (int r = 0; r < 4; r++) {
        float bias = gb[p0 + ty * 4 + r];
        float* dst = g_g + ((size_t)b * 1024 + p0 + ty * 4 + r) * Vv + n0 + tx * 8;
#pragma unroll
        for (int c = 0; c < 8; c++) dst[c] = acc[r][c] + bias;
    }
}

// ---- fused add(SEP,TEP) + LayerNorm(256) + GLU -> h_pad (warp per row) ----
__global__ __launch_bounds__(256) void k_lnglu(int l, const float* __restrict__ lng,
                                               const float* __restrict__ lnb) {
    int w = threadIdx.x >> 5, lane = threadIdx.x & 31;
    int row = blockIdx.x * 8 + w;                 // 0..BT*V-1
    int bt = row >> 9, v = row & 511;
    int b = bt / Tt, t = bt % Tt;
    const float* zr = g_z + (size_t)row * C2;
    const float* sp = g_sep + ((size_t)l * Vv + v) * C2;
    const float* tp = g_tep + ((size_t)l * BT + bt) * C2;
    float val[8];
    float sum = 0.f;
#pragma unroll
    for (int q = 0; q < 8; q++) {
        int c2 = q * 32 + lane;
        val[q] = zr[c2] + sp[c2] + tp[c2];
        sum += val[q];
    }
#pragma unroll
    for (int o = 16; o; o >>= 1) sum += __shfl_xor_sync(0xffffffffu, sum, o);
    float mean = sum * (1.f / 256.f);
    float s2 = 0.f;
#pragma unroll
    for (int q = 0; q < 8; q++) { float df = val[q] - mean; s2 += df * df; }
#pragma unroll
    for (int o = 16; o; o >>= 1) s2 += __shfl_xor_sync(0xffffffffu, s2, o);
    float rstd = rsqrtf(s2 * (1.f / 256.f) + 1e-5f);
    float y[8];
#pragma unroll
    for (int q = 0; q < 8; q++) {
        int c2 = q * 32 + lane;
        y[q] = (val[q] - mean) * rstd * lng[l * C2 + c2] + lnb[l * C2 + c2];
    }
    float* hp = g_hpad + (((size_t)b * TPAD + BETA + t) * Vv + v) * Cc;
#pragma unroll
    for (int q = 0; q < 4; q++) hp[q * 32 + lane] = y[q] * sigm(y[q + 4]);
}

// ---- GFS GLU: skip[b][slot*C+o][v] = (gb[o]+gw[o,:]·s) * sigm(gb[o+C]+gw[o+C,:]·s)
__global__ __launch_bounds__(128) void k_gfs_glu(int slot, const float* __restrict__ gw,
                                                 const float* __restrict__ gb) {
    int b = blockIdx.x >> 6;
    int v0 = (blockIdx.x & 63) * 8;
    __shared__ float s8[8][128];
    int o = threadIdx.x;
#pragma unroll
    for (int vi = 0; vi < 8; vi++)
        s8[vi][o] = g_s[((size_t)b * Vv + v0 + vi) * Cc + o];
    __syncthreads();
    float al[8], ar[8];
    float bl = gb[o], br = gb[o + 128];
#pragma unroll
    for (int vi = 0; vi < 8; vi++) { al[vi] = bl; ar[vi] = br; }
    const float* wl = gw + (size_t)o * 128;
    const float* wr = gw + (size_t)(o + 128) * 128;
    for (int c = 0; c < 128; c++) {
        float a = wl[c], bw = wr[c];
#pragma unroll
        for (int vi = 0; vi < 8; vi++) {
            float sv = s8[vi][c];
            al[vi] += a * sv;
            ar[vi] += bw * sv;
        }
    }
#pragma unroll
    for (int vi = 0; vi < 8; vi++)
        g_skip[((size_t)b * 512 + slot * 128 + o) * Vv + v0 + vi] = al[vi] * sigm(ar[vi]);
}

// ---- output head: out[b][r][v] = out_b[r] + sum_q out_w[r,q] * glu(g) ----
__global__ __launch_bounds__(512) void k_out(const float* __restrict__ ow,
                                             const float* __restrict__ ob,
                                             float* __restrict__ out) {
    __shared__ float ws[PP * 512];
    int b = blockIdx.x;
    int v = threadIdx.x;
    for (int i = v; i < PP * 512; i += 512) ws[i] = ow[i];
    __syncthreads();
    float acc[PP];
#pragma unroll
    for (int r = 0; r < PP; r++) acc[r] = ob[r];
    const float* gB = g_g + (size_t)b * 1024 * Vv;
    for (int q = 0; q < 512; q++) {
        float gl = gB[(size_t)q * Vv + v];
        float gr = gB[(size_t)(512 + q) * Vv + v];
        float gate = gl * sigm(gr);
#pragma unroll
        for (int r = 0; r < PP; r++) acc[r] += ws[r * 512 + q] * gate;
    }
#pragma unroll
    for (int r = 0; r < PP; r++) out[((size_t)b * PP + r) * Vv + v] = acc[r];
}

// ---------------- orchestration ----------------
extern "C" void kernel_launch(void* const* d_in, const int* in_sizes, int n_in,
                              void* d_out, int out_size) {
    const float* x          = (const float*)d_in[0];
    const float* sape       = (const float*)d_in[1];
    const float* tape       = (const float*)d_in[2];
    const float* srpe       = (const float*)d_in[3];
    const float* trpe       = (const float*)d_in[4];
    const float* range_mask = (const float*)d_in[7];
    const float* input_w    = (const float*)d_in[8];
    const float* input_b    = (const float*)d_in[9];
    const float* fs0_fc_w   = (const float*)d_in[10];
    const float* fs0_fc_b   = (const float*)d_in[11];
    const float* fs0_glu_w  = (const float*)d_in[12];
    const float* fs0_glu_b  = (const float*)d_in[13];
    const float* mus        = (const float*)d_in[14];
    const float* isgs       = (const float*)d_in[15];
    const float* xproj_w    = (const float*)d_in[16];
    const float* xproj_b    = (const float*)d_in[17];
    const float* seproj_w   = (const float*)d_in[18];
    const float* teproj_w   = (const float*)d_in[19];
    const float* ln_g       = (const float*)d_in[20];
    const float* ln_b       = (const float*)d_in[21];
    const float* fs_fc_w    = (const float*)d_in[22];
    const float* fs_fc_b    = (const float*)d_in[23];
    const float* fs_glu_w   = (const float*)d_in[24];
    const float* fs_glu_b   = (const float*)d_in[25];
    const float* glu_w      = (const float*)d_in[26];
    const float* glu_b      = (const float*)d_in[27];
    const float* out_w      = (const float*)d_in[28];
    const float* out_b      = (const float*)d_in[29];
    float* out = (float*)d_out;

    // setup
    k_input<<<(Bb * TPAD * Vv * Cc) / 256, 256>>>(x, input_w, input_b);
    k_fwT<<<(4 * Cc * KTC) / 256, 256>>>(fs0_fc_w, fs_fc_w);
    k_buildE<<<LL * Vv * TSZ, 512>>>(sape, srpe, trpe, range_mask, mus, isgs);
    k_scalars<<<3, 96>>>(tape, mus, isgs);
    {
        int n = LL * Vv * C2 + LL * BT * C2;
        k_septep<<<(n + 255) / 256, 256>>>(sape, tape, seproj_w, teproj_w, xproj_b);
    }

    // skip 0 (GFS on initial h)
    k_gfs_s<<<dim3(8, 8), 256>>>(0, fs0_fc_b);
    k_gfs_glu<<<Bb * 64, 128>>>(0, fs0_glu_w, fs0_glu_b);

    // layers
    for (int l = 0; l < LL; l++) {
        k_agg<<<dim3(8, BT), 256>>>(l);
        k_zgemm<<<dim3(BT * Vv / 64, 2), 256>>>(xproj_w + (size_t)l * Cc * C2);
        k_lnglu<<<BT * Vv / 8, 256>>>(l, ln_g, ln_b);
        k_gfs_s<<<dim3(8, 8), 256>>>(l + 1, fs_fc_b + l * Cc);
        k_gfs_glu<<<Bb * 64, 128>>>(l + 1, fs_glu_w + (size_t)l * 2 * Cc * Cc,
                                    fs_glu_b + l * 2 * Cc);
    }

    // head
    k_headg<<<dim3(16, 32), 256>>>(glu_w, glu_b);
    k_out<<<Bb, 512>>>(out_w, out_b, out);
}

// round 4
// speedup vs baseline: 2.1548x; 2.1548x over previous
#include <cuda_runtime.h>
#include <math.h>
#include <cstdint>

// ---------------- problem constants ----------------
#define Bb   8
#define Tt   12
#define Vv   512
#define Cc   128
#define TSZ  3
#define LL   3
#define PP   12
#define BETA 2
#define TPAD (Tt + BETA)   // 14
#define C2   256
#define KV   (TSZ * Vv)    // 1536
#define KTC  (Tt * Cc)     // 1536
#define BT   (Bb * Tt)     // 96
#define PADK 36

// ---------------- device scratch (static; no runtime alloc) ----------------
__device__ float g_hpad[Bb * TPAD * Vv * Cc];          // [b][tp][v][c]
__device__ float g_hpadT[Bb * TPAD * Cc * Vv];         // [b][tp][c][v]
__device__ float g_E[LL * Vv * KV];
__device__ float g_agg[BT * Vv * Cc];
__device__ float g_z[BT * Vv * C2];
__device__ float g_s[Bb * Vv * Cc];
__device__ float g_skipT[Bb * Vv * 512];               // [b][v][o]
__device__ float g_g[Bb * 1024 * Vv];
__device__ float g_sep[LL * Vv * C2];
__device__ float g_tep[LL * BT * C2];
__device__ float g_ascal[LL * BT];
__device__ float g_wk[LL * BT * TSZ];
__device__ float g_xwT[LL * C2 * Cc];                  // [l][n][k]

__device__ __forceinline__ float sigm(float x) { return 1.f / (1.f + expf(-x)); }

// ================= warp-level tf32 MMA machinery =================
__device__ __forceinline__ uint32_t f2tf(float v) {
    uint32_t r;
    asm("cvt.rna.tf32.f32 %0, %1;" : "=r"(r) : "f"(v));
    return r;
}

// Fill a 128x32 K-major tile into SMEM [128][PADK] as tf32, scaled by w.
__device__ __forceinline__ void fill_tile(uint32_t* sm, const float* __restrict__ src,
                                          int rstride, float w, int tid) {
#pragma unroll
    for (int q = 0; q < 4; q++) {
        int idx = q * 256 + tid;
        int r = idx >> 3;
        int kg = (idx & 7) << 2;
        float4 v = *(const float4*)(src + (size_t)r * rstride + kg);
        uint4 u;
        u.x = f2tf(v.x * w); u.y = f2tf(v.y * w);
        u.z = f2tf(v.z * w); u.w = f2tf(v.w * w);
        *(uint4*)(sm + r * PADK + kg) = u;
    }
}

// One K=32 chunk of 128x128 MMA. 8 warps: wm=wid>>2 (2x64 rows), wn=wid&3 (4x32 cols).
__device__ __forceinline__ void mma_chunk(const uint32_t* As, const uint32_t* Bs,
                                          float acc[4][4][4], int wm, int wn, int lane) {
    int g = lane >> 2, c = lane & 3;
#pragma unroll
    for (int kk = 0; kk < 4; kk++) {
        uint32_t a[4][4];
#pragma unroll
        for (int mt = 0; mt < 4; mt++) {
            const uint32_t* ap = As + (wm * 64 + mt * 16 + g) * PADK + kk * 8 + c;
            a[mt][0] = ap[0];
            a[mt][1] = ap[8 * PADK];
            a[mt][2] = ap[4];
            a[mt][3] = ap[8 * PADK + 4];
        }
#pragma unroll
        for (int nt = 0; nt < 4; nt++) {
            const uint32_t* bp = Bs + (wn * 32 + nt * 8 + g) * PADK + kk * 8 + c;
            uint32_t b0 = bp[0], b1 = bp[4];
#pragma unroll
            for (int mt = 0; mt < 4; mt++) {
                asm volatile(
                    "mma.sync.aligned.m16n8k8.row.col.f32.tf32.tf32.f32 "
                    "{%0,%1,%2,%3}, {%4,%5,%6,%7}, {%8,%9}, {%0,%1,%2,%3};"
                    : "+f"(acc[mt][nt][0]), "+f"(acc[mt][nt][1]),
                      "+f"(acc[mt][nt][2]), "+f"(acc[mt][nt][3])
                    : "r"(a[mt][0]), "r"(a[mt][1]), "r"(a[mt][2]), "r"(a[mt][3]),
                      "r"(b0), "r"(b1));
            }
        }
    }
}

#define ACC_INIT(acc) \
    _Pragma("unroll") for (int _m = 0; _m < 4; _m++) \
    _Pragma("unroll") for (int _n = 0; _n < 4; _n++) \
    _Pragma("unroll") for (int _e = 0; _e < 4; _e++) acc[_m][_n][_e] = 0.f;

// ---------------- h_pad = [zeros(BETA) ; x@input_w + input_b] ----------------
__global__ void k_input(const float* __restrict__ x, const float* __restrict__ iw,
                        const float* __restrict__ ib) {
    int idx = blockIdx.x * blockDim.x + threadIdx.x;
    if (idx >= Bb * TPAD * Vv * Cc) return;
    int c = idx & 127;
    int rest = idx >> 7;
    int v = rest & 511;
    int bt = rest >> 9;
    int tp = bt % TPAD;
    int b  = bt / TPAD;
    float val = 0.f;
    if (tp >= BETA) {
        float xv = x[(b * Tt + (tp - BETA)) * Vv + v];
        val = xv * iw[c] + ib[c];
    }
    g_hpad[idx] = val;
    g_hpadT[((size_t)(b * TPAD + tp) * Cc + c) * Vv + v] = val;
}

// ---------------- xwT[l][n][k] = xproj_w[l][k][n] ----------------
__global__ void k_xwT(const float* __restrict__ xw) {
    int idx = blockIdx.x * blockDim.x + threadIdx.x;
    if (idx >= LL * C2 * Cc) return;
    int l = idx / (C2 * Cc);
    int n = (idx / Cc) % C2;
    int k = idx % Cc;
    g_xwT[idx] = xw[((size_t)l * Cc + k) * C2 + n];
}

// ---------------- E[l][j][k*V+i] ----------------
__global__ void k_buildE(const float* __restrict__ sape, const float* __restrict__ srpe,
                         const float* __restrict__ trpe, const float* __restrict__ mask,
                         const float* __restrict__ mus, const float* __restrict__ isgs) {
    int blk = blockIdx.x;
    int l = blk / (Vv * 3);
    int rem = blk % (Vv * 3);
    int j = rem / 3, k = rem % 3;
    int i = threadIdx.x;
    __shared__ float mu[48], is[48];
    if (threadIdx.x < 48) { mu[threadIdx.x] = mus[l * 48 + threadIdx.x];
                            is[threadIdx.x] = isgs[l * 48 + threadIdx.x]; }
    __syncthreads();
    float gi = 0.f, gj = 0.f, ge = 0.f, gtr = 0.f;
#pragma unroll
    for (int q = 0; q < 8; q++) {
        float df;
        df = sape[i * 8 + q] - mu[q];        gi  += -0.5f * df * df * is[q] * is[q];
        df = sape[j * 8 + q] - mu[8 + q];    gj  += -0.5f * df * df * is[8 + q] * is[8 + q];
        df = srpe[((size_t)i * Vv + j) * 8 + q] - mu[32 + q];
                                             ge  += -0.5f * df * df * is[32 + q] * is[32 + q];
        df = trpe[k * 8 + q] - mu[40 + q];   gtr += -0.5f * df * df * is[40 + q] * is[40 + q];
    }
    float m = mask[j * KV + k * Vv + i];
    g_E[((size_t)l * Vv + j) * KV + k * Vv + i] = m * expf(gi + gj + ge + gtr);
}

// ---------------- per-(l,b,t) scalars ----------------
__global__ void k_scalars(const float* __restrict__ tape, const float* __restrict__ mus,
                          const float* __restrict__ isgs) {
    int idx = blockIdx.x * blockDim.x + threadIdx.x;
    if (idx >= LL * BT) return;
    int l = idx / BT, bt = idx % BT;
    int b = bt / Tt, t = bt % Tt;
    const float* mu2 = mus + (l * 6 + 2) * 8; const float* is2 = isgs + (l * 6 + 2) * 8;
    const float* mu3 = mus + (l * 6 + 3) * 8; const float* is3 = isgs + (l * 6 + 3) * 8;
    float gti = 0.f;
    const float* tp = tape + (b * Tt + t) * 8;
#pragma unroll
    for (int q = 0; q < 8; q++) { float df = tp[q] - mu2[q]; gti += -0.5f * df * df * is2[q] * is2[q]; }
    g_ascal[idx] = expf(gti);
    for (int k = 0; k < 3; k++) {
        int s = t + k;
        float gtj = 0.f;
#pragma unroll
        for (int q = 0; q < 8; q++) {
            float e = (s < BETA) ? 0.f : tape[(b * Tt + (s - BETA)) * 8 + q];
            float df = e - mu3[q];
            gtj += -0.5f * df * df * is3[q] * is3[q];
        }
        g_wk[idx * 3 + k] = expf(gtj);
    }
}

// ---------------- SEP / TEP ----------------
__global__ void k_septep(const float* __restrict__ sape, const float* __restrict__ tape,
                         const float* __restrict__ sew, const float* __restrict__ tew,
                         const float* __restrict__ xpb) {
    int idx = blockIdx.x * blockDim.x + threadIdx.x;
    const int NSEP = LL * Vv * C2;
    const int NTEP = LL * BT * C2;
    if (idx < NSEP) {
        int l = idx / (Vv * C2);
        int v = (idx / C2) % Vv;
        int c2 = idx % C2;
        float acc = 0.f;
#pragma unroll
        for (int q = 0; q < 8; q++) acc += sape[v * 8 + q] * sew[(l * 8 + q) * C2 + c2];
        g_sep[idx] = acc;
    } else if (idx < NSEP + NTEP) {
        int jdx = idx - NSEP;
        int l = jdx / (BT * C2);
        int bt = (jdx / C2) % BT;
        int c2 = jdx % C2;
        float acc = xpb[l * C2 + c2];
#pragma unroll
        for (int q = 0; q < 8; q++) acc += tape[bt * 8 + q] * tew[(l * 8 + q) * C2 + c2];
        g_tep[jdx] = acc;
    }
}

// ============ MMA GEMM kernels (128x128 tiles) ============

// agg[bt][j][c] = ascal * sum_kv (wk[k]*E[j,kv]) * hpadT[b,t+k,c,i]
__global__ __launch_bounds__(256) void k_agg_mma(int l) {
    __shared__ __align__(16) uint32_t As[128 * PADK];
    __shared__ __align__(16) uint32_t Bs[128 * PADK];
    int tid = threadIdx.x;
    int wid = tid >> 5, lane = tid & 31;
    int wm = wid >> 2, wn = wid & 3;
    int bt = blockIdx.y, b = bt / Tt, t = bt % Tt;
    int j0 = blockIdx.x * 128;
    float acc[4][4][4];
    ACC_INIT(acc);
    const float* Abase = g_E + ((size_t)l * Vv + j0) * KV;
    for (int ch = 0; ch < 48; ch++) {
        int k = ch >> 4;
        int i0 = (ch & 15) * 32;
        float w = g_wk[(l * BT + bt) * 3 + k];
        fill_tile(As, Abase + ch * 32, KV, w, tid);
        fill_tile(Bs, g_hpadT + (size_t)(b * TPAD + t + k) * Cc * Vv + i0, Vv, 1.f, tid);
        __syncthreads();
        mma_chunk(As, Bs, acc, wm, wn, lane);
        __syncthreads();
    }
    float ascal = g_ascal[l * BT + bt];
    int g = lane >> 2, c = lane & 3;
#pragma unroll
    for (int mt = 0; mt < 4; mt++) {
#pragma unroll
        for (int nt = 0; nt < 4; nt++) {
            int row = wm * 64 + mt * 16 + g;
            int col = wn * 32 + nt * 8 + 2 * c;
            float* d0 = g_agg + ((size_t)bt * Vv + j0 + row) * Cc + col;
            float* d1 = d0 + 8 * Cc;
            *(float2*)d0 = make_float2(acc[mt][nt][0] * ascal, acc[mt][nt][1] * ascal);
            *(float2*)d1 = make_float2(acc[mt][nt][2] * ascal, acc[mt][nt][3] * ascal);
        }
    }
}

// z = agg @ xproj_w[l]: M=BT*V (grid.x*128), N=256 (grid.y*128), K=128
__global__ __launch_bounds__(256) void k_zgemm_mma(int l) {
    __shared__ __align__(16) uint32_t As[128 * PADK];
    __shared__ __align__(16) uint32_t Bs[128 * PADK];
    int tid = threadIdx.x;
    int wid = tid >> 5, lane = tid & 31;
    int wm = wid >> 2, wn = wid & 3;
    int m0 = blockIdx.x * 128;
    int n0 = blockIdx.y * 128;
    float acc[4][4][4];
    ACC_INIT(acc);
    const float* Bbase = g_xwT + (size_t)l * C2 * Cc + (size_t)n0 * Cc;
    for (int ch = 0; ch < 4; ch++) {
        fill_tile(As, g_agg + (size_t)m0 * Cc + ch * 32, Cc, 1.f, tid);
        fill_tile(Bs, Bbase + ch * 32, Cc, 1.f, tid);
        __syncthreads();
        mma_chunk(As, Bs, acc, wm, wn, lane);
        __syncthreads();
    }
    int g = lane >> 2, c = lane & 3;
#pragma unroll
    for (int mt = 0; mt < 4; mt++) {
#pragma unroll
        for (int nt = 0; nt < 4; nt++) {
            int row = wm * 64 + mt * 16 + g;
            int col = wn * 32 + nt * 8 + 2 * c;
            float* d0 = g_z + (size_t)(m0 + row) * C2 + n0 + col;
            float* d1 = d0 + 8 * C2;
            *(float2*)d0 = make_float2(acc[mt][nt][0], acc[mt][nt][1]);
            *(float2*)d1 = make_float2(acc[mt][nt][2], acc[mt][nt][3]);
        }
    }
}

// GFS fc: s[b][v][o] = fb[o] + sum_{t,c} hpad[b,2+t,v,c]*fcw[o][t*C+c]
__global__ __launch_bounds__(256) void k_gfs_mma(const float* __restrict__ fcw,
                                                 const float* __restrict__ fb) {
    __shared__ __align__(16) uint32_t As[128 * PADK];
    __shared__ __align__(16) uint32_t Bs[128 * PADK];
    int tid = threadIdx.x;
    int wid = tid >> 5, lane = tid & 31;
    int wm = wid >> 2, wn = wid & 3;
    int v0 = blockIdx.x * 128;
    int b = blockIdx.y;
    float acc[4][4][4];
    ACC_INIT(acc);
    for (int ch = 0; ch < 48; ch++) {
        int t = ch >> 2;
        int coff = (ch & 3) * 32;
        fill_tile(As, g_hpad + ((size_t)(b * TPAD + BETA + t) * Vv + v0) * Cc + coff,
                  Cc, 1.f, tid);
        fill_tile(Bs, fcw + ch * 32, KTC, 1.f, tid);
        __syncthreads();
        mma_chunk(As, Bs, acc, wm, wn, lane);
        __syncthreads();
    }
    int g = lane >> 2, c = lane & 3;
#pragma unroll
    for (int mt = 0; mt < 4; mt++) {
#pragma unroll
        for (int nt = 0; nt < 4; nt++) {
            int row = wm * 64 + mt * 16 + g;
            int col = wn * 32 + nt * 8 + 2 * c;
            float b0 = fb[col], b1 = fb[col + 1];
            float* d0 = g_s + ((size_t)b * Vv + v0 + row) * Cc + col;
            float* d1 = d0 + 8 * Cc;
            *(float2*)d0 = make_float2(acc[mt][nt][0] + b0, acc[mt][nt][1] + b1);
            *(float2*)d1 = make_float2(acc[mt][nt][2] + b0, acc[mt][nt][3] + b1);
        }
    }
}

// head: g[b][p][v] = gb[p] + sum_o gw[p][o]*skipT[b][v][o]. M=1024(p), N=512(v), K=512
__global__ __launch_bounds__(256) void k_headg_mma(const float* __restrict__ gw,
                                                   const float* __restrict__ gb) {
    __shared__ __align__(16) uint32_t As[128 * PADK];
    __shared__ __align__(16) uint32_t Bs[128 * PADK];
    int tid = threadIdx.x;
    int wid = tid >> 5, lane = tid & 31;
    int wm = wid >> 2, wn = wid & 3;
    int p0 = blockIdx.x * 128;
    int b = blockIdx.y >> 2;
    int n0 = (blockIdx.y & 3) * 128;
    float acc[4][4][4];
    ACC_INIT(acc);
    for (int ch = 0; ch < 16; ch++) {
        fill_tile(As, gw + (size_t)p0 * 512 + ch * 32, 512, 1.f, tid);
        fill_tile(Bs, g_skipT + ((size_t)b * Vv + n0) * 512 + ch * 32, 512, 1.f, tid);
        __syncthreads();
        mma_chunk(As, Bs, acc, wm, wn, lane);
        __syncthreads();
    }
    int g = lane >> 2, c = lane & 3;
#pragma unroll
    for (int mt = 0; mt < 4; mt++) {
#pragma unroll
        for (int nt = 0; nt < 4; nt++) {
            int row = wm * 64 + mt * 16 + g;
            int col = wn * 32 + nt * 8 + 2 * c;
            float bi0 = gb[p0 + row], bi1 = gb[p0 + row + 8];
            float* d0 = g_g + ((size_t)b * 1024 + p0 + row) * Vv + n0 + col;
            float* d1 = d0 + 8 * Vv;
            *(float2*)d0 = make_float2(acc[mt][nt][0] + bi0, acc[mt][nt][1] + bi0);
            *(float2*)d1 = make_float2(acc[mt][nt][2] + bi1, acc[mt][nt][3] + bi1);
        }
    }
}

// ---- fused add + LayerNorm + GLU -> h_pad and h_padT ----
__global__ __launch_bounds__(256) void k_lnglu(int l, const float* __restrict__ lng,
                                               const float* __restrict__ lnb) {
    int w = threadIdx.x >> 5, lane = threadIdx.x & 31;
    int row = blockIdx.x * 8 + w;
    int bt = row >> 9, v = row & 511;
    int b = bt / Tt, t = bt % Tt;
    const float* zr = g_z + (size_t)row * C2;
    const float* sp = g_sep + ((size_t)l * Vv + v) * C2;
    const float* tp = g_tep + ((size_t)l * BT + bt) * C2;
    float val[8];
    float sum = 0.f;
#pragma unroll
    for (int q = 0; q < 8; q++) {
        int c2 = q * 32 + lane;
        val[q] = zr[c2] + sp[c2] + tp[c2];
        sum += val[q];
    }
#pragma unroll
    for (int o = 16; o; o >>= 1) sum += __shfl_xor_sync(0xffffffffu, sum, o);
    float mean = sum * (1.f / 256.f);
    float s2 = 0.f;
#pragma unroll
    for (int q = 0; q < 8; q++) { float df = val[q] - mean; s2 += df * df; }
#pragma unroll
    for (int o = 16; o; o >>= 1) s2 += __shfl_xor_sync(0xffffffffu, s2, o);
    float rstd = rsqrtf(s2 * (1.f / 256.f) + 1e-5f);
    float y[8];
#pragma unroll
    for (int q = 0; q < 8; q++) {
        int c2 = q * 32 + lane;
        y[q] = (val[q] - mean) * rstd * lng[l * C2 + c2] + lnb[l * C2 + c2];
    }
    size_t slab = (size_t)(b * TPAD + BETA + t);
    float* hp = g_hpad + (slab * Vv + v) * Cc;
#pragma unroll
    for (int q = 0; q < 4; q++) {
        float hv = y[q] * sigm(y[q + 4]);
        int c = q * 32 + lane;
        hp[c] = hv;
        g_hpadT[(slab * Cc + c) * Vv + v] = hv;
    }
}

// ---- GFS GLU -> skipT[b][v][slot*128+o] ----
__global__ __launch_bounds__(128) void k_gfs_glu(int slot, const float* __restrict__ gw,
                                                 const float* __restrict__ gb) {
    int b = blockIdx.x >> 6;
    int v0 = (blockIdx.x & 63) * 8;
    __shared__ float s8[8][128];
    int o = threadIdx.x;
#pragma unroll
    for (int vi = 0; vi < 8; vi++)
        s8[vi][o] = g_s[((size_t)b * Vv + v0 + vi) * Cc + o];
    __syncthreads();
    float al[8], ar[8];
    float bl = gb[o], br = gb[o + 128];
#pragma unroll
    for (int vi = 0; vi < 8; vi++) { al[vi] = bl; ar[vi] = br; }
    const float* wl = gw + (size_t)o * 128;
    const float* wr = gw + (size_t)(o + 128) * 128;
    for (int c = 0; c < 128; c++) {
        float a = wl[c], bw = wr[c];
#pragma unroll
        for (int vi = 0; vi < 8; vi++) {
            float sv = s8[vi][c];
            al[vi] += a * sv;
            ar[vi] += bw * sv;
        }
    }
#pragma unroll
    for (int vi = 0; vi < 8; vi++)
        g_skipT[((size_t)b * Vv + v0 + vi) * 512 + slot * 128 + o] = al[vi] * sigm(ar[vi]);
}

// ---- output head ----
__global__ __launch_bounds__(512) void k_out(const float* __restrict__ ow,
                                             const float* __restrict__ ob,
                                             float* __restrict__ out) {
    __shared__ float ws[PP * 512];
    int b = blockIdx.x;
    int v = threadIdx.x;
    for (int i = v; i < PP * 512; i += 512) ws[i] = ow[i];
    __syncthreads();
    float acc[PP];
#pragma unroll
    for (int r = 0; r < PP; r++) acc[r] = ob[r];
    const float* gB = g_g + (size_t)b * 1024 * Vv;
    for (int q = 0; q < 512; q++) {
        float gl = gB[(size_t)q * Vv + v];
        float gr = gB[(size_t)(512 + q) * Vv + v];
        float gate = gl * sigm(gr);
#pragma unroll
        for (int r = 0; r < PP; r++) acc[r] += ws[r * 512 + q] * gate;
    }
#pragma unroll
    for (int r = 0; r < PP; r++) out[((size_t)b * PP + r) * Vv + v] = acc[r];
}

// ---------------- orchestration ----------------
extern "C" void kernel_launch(void* const* d_in, const int* in_sizes, int n_in,
                              void* d_out, int out_size) {
    const float* x          = (const float*)d_in[0];
    const float* sape       = (const float*)d_in[1];
    const float* tape       = (const float*)d_in[2];
    const float* srpe       = (const float*)d_in[3];
    const float* trpe       = (const float*)d_in[4];
    const float* range_mask = (const float*)d_in[7];
    const float* input_w    = (const float*)d_in[8];
    const float* input_b    = (const float*)d_in[9];
    const float* fs0_fc_w   = (const float*)d_in[10];
    const float* fs0_fc_b   = (const float*)d_in[11];
    const float* fs0_glu_w  = (const float*)d_in[12];
    const float* fs0_glu_b  = (const float*)d_in[13];
    const float* mus        = (const float*)d_in[14];
    const float* isgs       = (const float*)d_in[15];
    const float* xproj_w    = (const float*)d_in[16];
    const float* xproj_b    = (const float*)d_in[17];
    const float* seproj_w   = (const float*)d_in[18];
    const float* teproj_w   = (const float*)d_in[19];
    const float* ln_g       = (const float*)d_in[20];
    const float* ln_b       = (const float*)d_in[21];
    const float* fs_fc_w    = (const float*)d_in[22];
    const float* fs_fc_b    = (const float*)d_in[23];
    const float* fs_glu_w   = (const float*)d_in[24];
    const float* fs_glu_b   = (const float*)d_in[25];
    const float* glu_w      = (const float*)d_in[26];
    const float* glu_b      = (const float*)d_in[27];
    const float* out_w      = (const float*)d_in[28];
    const float* out_b      = (const float*)d_in[29];
    float* out = (float*)d_out;

    // setup
    k_input<<<(Bb * TPAD * Vv * Cc) / 256, 256>>>(x, input_w, input_b);
    k_xwT<<<(LL * C2 * Cc) / 256, 256>>>(xproj_w);
    k_buildE<<<LL * Vv * TSZ, 512>>>(sape, srpe, trpe, range_mask, mus, isgs);
    k_scalars<<<3, 96>>>(tape, mus, isgs);
    {
        int n = LL * Vv * C2 + LL * BT * C2;
        k_septep<<<(n + 255) / 256, 256>>>(sape, tape, seproj_w, teproj_w, xproj_b);
    }

    // skip 0
    k_gfs_mma<<<dim3(4, Bb), 256>>>(fs0_fc_w, fs0_fc_b);
    k_gfs_glu<<<Bb * 64, 128>>>(0, fs0_glu_w, fs0_glu_b);

    // layers
    for (int l = 0; l < LL; l++) {
        k_agg_mma<<<dim3(4, BT), 256>>>(l);
        k_zgemm_mma<<<dim3(BT * Vv / 128, 2), 256>>>(l);
        k_lnglu<<<BT * Vv / 8, 256>>>(l, ln_g, ln_b);
        k_gfs_mma<<<dim3(4, Bb), 256>>>(fs_fc_w + (size_t)l * Cc * KTC, fs_fc_b + l * Cc);
        k_gfs_glu<<<Bb * 64, 128>>>(l + 1, fs_glu_w + (size_t)l * 2 * Cc * Cc,
                                    fs_glu_b + l * 2 * Cc);
    }

    // head
    k_headg_mma<<<dim3(8, 32), 256>>>(glu_w, glu_b);
    k_out<<<Bb, 512>>>(out_w, out_b, out);
}

// round 5
// speedup vs baseline: 3.2979x; 1.5304x over previous
#include <cuda_runtime.h>
#include <math.h>
#include <cstdint>

// ---------------- problem constants ----------------
#define Bb   8
#define Tt   12
#define Vv   512
#define Cc   128
#define TSZ  3
#define LL   3
#define PP   12
#define BETA 2
#define TPAD (Tt + BETA)   // 14
#define C2   256
#define KV   (TSZ * Vv)    // 1536
#define KTC  (Tt * Cc)     // 1536
#define BT   (Bb * Tt)     // 96
#define PADK 36
#define KSPL 6             // gfs split-K
#define QSPL 4             // out split-q

#define TILE_BYTES (128 * PADK * 4)        // 18432
#define SMEM_PIPE  (4 * TILE_BYTES)        // 73728 (2 stages x A,B)

// ---------------- device scratch (static; no runtime alloc) ----------------
__device__ __align__(16) uint32_t g_ht [Bb * TPAD * Vv * Cc];   // tf32 h [b][tp][v][c]
__device__ __align__(16) uint32_t g_hTt[Bb * TPAD * Cc * Vv];   // tf32 h [b][tp][c][v]
__device__ __align__(16) uint32_t g_Et [LL * Vv * KV];          // tf32 E
__device__ __align__(16) uint32_t g_aggt[BT * Vv * Cc];         // tf32 agg
__device__ __align__(16) float    g_z[BT * Vv * C2];
__device__ __align__(16) float    g_s[Bb * Vv * Cc];
__device__ __align__(16) float    g_spart[KSPL * Bb * Vv * Cc];
__device__ __align__(16) uint32_t g_skipTt[Bb * Vv * 512];      // tf32 [b][v][o]
__device__ __align__(16) float    g_g[Bb * 1024 * Vv];
__device__ __align__(16) float    g_sep[LL * Vv * C2];
__device__ __align__(16) float    g_tep[LL * BT * C2];
__device__ float    g_ascal[LL * BT];
__device__ float    g_wk[LL * BT * TSZ];
__device__ __align__(16) uint32_t g_xwTt[LL * C2 * Cc];         // tf32 [l][n][k]
__device__ __align__(16) uint32_t g_fwt[4 * Cc * KTC];          // tf32 [s][o][tc]
__device__ __align__(16) uint32_t g_gwt[1024 * 512];            // tf32 glu_w
__device__ __align__(16) float    g_opart[QSPL * Bb * PP * Vv];

__device__ __forceinline__ float sigm(float x) { return 1.f / (1.f + expf(-x)); }
__device__ __forceinline__ uint32_t f2tf(float v) {
    uint32_t r;
    asm("cvt.rna.tf32.f32 %0, %1;" : "=r"(r) : "f"(v));
    return r;
}
__device__ __forceinline__ uint32_t smem_u32(const void* p) {
    uint32_t a;
    asm("{ .reg .u64 t; cvta.to.shared.u64 t, %1; cvt.u32.u64 %0, t; }" : "=r"(a) : "l"(p));
    return a;
}
__device__ __forceinline__ void cpa16(uint32_t dst, const void* src) {
    asm volatile("cp.async.cg.shared.global [%0], [%1], 16;" :: "r"(dst), "l"(src));
}
#define CP_COMMIT() asm volatile("cp.async.commit_group;" ::: "memory")
#define CP_WAIT0()  asm volatile("cp.async.wait_group 0;" ::: "memory")
#define CP_WAIT1()  asm volatile("cp.async.wait_group 1;" ::: "memory")

// Fill a 128x32 tf32 tile into smem stage (byte addr smdst), 16B cp.async x4/thread.
__device__ __forceinline__ void fill_async(uint32_t smdst, const uint32_t* __restrict__ src,
                                           int rstride, int tid) {
#pragma unroll
    for (int q = 0; q < 4; q++) {
        int idx = q * 256 + tid;
        int r = idx >> 3;
        int c4 = (idx & 7) << 2;
        cpa16(smdst + (uint32_t)(r * PADK + c4) * 4, src + (size_t)r * rstride + c4);
    }
}

// One K=32 chunk of 128x128 MMA. 8 warps: wm=wid>>2 (2x64 rows), wn=wid&3 (4x32 cols).
// SCALE: multiply A fragments by w (re-rounded to tf32).
template <bool SCALE>
__device__ __forceinline__ void mma_chunk(const uint32_t* As, const uint32_t* Bs,
                                          float acc[4][4][4], int wm, int wn, int lane,
                                          float w) {
    int g = lane >> 2, c = lane & 3;
#pragma unroll
    for (int kk = 0; kk < 4; kk++) {
        uint32_t a[4][4];
#pragma unroll
        for (int mt = 0; mt < 4; mt++) {
            const uint32_t* ap = As + (wm * 64 + mt * 16 + g) * PADK + kk * 8 + c;
            a[mt][0] = ap[0];
            a[mt][1] = ap[8 * PADK];
            a[mt][2] = ap[4];
            a[mt][3] = ap[8 * PADK + 4];
            if (SCALE) {
#pragma unroll
                for (int e = 0; e < 4; e++)
                    a[mt][e] = f2tf(__uint_as_float(a[mt][e]) * w);
            }
        }
#pragma unroll
        for (int nt = 0; nt < 4; nt++) {
            const uint32_t* bp = Bs + (wn * 32 + nt * 8 + g) * PADK + kk * 8 + c;
            uint32_t b0 = bp[0], b1 = bp[4];
#pragma unroll
            for (int mt = 0; mt < 4; mt++) {
                asm volatile(
                    "mma.sync.aligned.m16n8k8.row.col.f32.tf32.tf32.f32 "
                    "{%0,%1,%2,%3}, {%4,%5,%6,%7}, {%8,%9}, {%0,%1,%2,%3};"
                    : "+f"(acc[mt][nt][0]), "+f"(acc[mt][nt][1]),
                      "+f"(acc[mt][nt][2]), "+f"(acc[mt][nt][3])
                    : "r"(a[mt][0]), "r"(a[mt][1]), "r"(a[mt][2]), "r"(a[mt][3]),
                      "r"(b0), "r"(b1));
            }
        }
    }
}

#define ACC_INIT(acc) \
    _Pragma("unroll") for (int _m = 0; _m < 4; _m++) \
    _Pragma("unroll") for (int _n = 0; _n < 4; _n++) \
    _Pragma("unroll") for (int _e = 0; _e < 4; _e++) acc[_m][_n][_e] = 0.f;

// ---------------- h_pad = [zeros ; x@input_w + input_b] (tf32, 2 layouts) ----------------
__global__ void k_input(const float* __restrict__ x, const float* __restrict__ iw,
                        const float* __restrict__ ib) {
    int idx = blockIdx.x * blockDim.x + threadIdx.x;
    if (idx >= Bb * TPAD * Vv * Cc) return;
    int c = idx & 127;
    int rest = idx >> 7;
    int v = rest & 511;
    int bt = rest >> 9;
    int tp = bt % TPAD;
    int b  = bt / TPAD;
    float val = 0.f;
    if (tp >= BETA) {
        float xv = x[(b * Tt + (tp - BETA)) * Vv + v];
        val = xv * iw[c] + ib[c];
    }
    uint32_t tv = f2tf(val);
    g_ht[idx] = tv;
    g_hTt[((size_t)(b * TPAD + tp) * Cc + c) * Vv + v] = tv;
}

// ---------------- weight conversions (once) ----------------
__global__ void k_cvtW(const float* __restrict__ xw, const float* __restrict__ fs0,
                       const float* __restrict__ fsl, const float* __restrict__ gw) {
    int idx = blockIdx.x * blockDim.x + threadIdx.x;
    const int N1 = LL * C2 * Cc;
    const int N2 = 4 * Cc * KTC;
    const int N3 = 1024 * 512;
    if (idx < N1) {
        int l = idx / (C2 * Cc);
        int n = (idx / Cc) % C2;
        int k = idx % Cc;
        g_xwTt[idx] = f2tf(xw[((size_t)l * Cc + k) * C2 + n]);
    } else if (idx < N1 + N2) {
        int j = idx - N1;
        int s = j / (Cc * KTC);
        int r = j % (Cc * KTC);
        float v = (s == 0) ? fs0[r] : fsl[(size_t)(s - 1) * Cc * KTC + r];
        g_fwt[j] = f2tf(v);
    } else if (idx < N1 + N2 + N3) {
        int j = idx - N1 - N2;
        g_gwt[j] = f2tf(gw[j]);
    }
}

// ---------------- E (tf32) ----------------
__global__ void k_buildE(const float* __restrict__ sape, const float* __restrict__ srpe,
                         const float* __restrict__ trpe, const float* __restrict__ mask,
                         const float* __restrict__ mus, const float* __restrict__ isgs) {
    int blk = blockIdx.x;
    int l = blk / (Vv * 3);
    int rem = blk % (Vv * 3);
    int j = rem / 3, k = rem % 3;
    int i = threadIdx.x;
    __shared__ float mu[48], is[48];
    if (threadIdx.x < 48) { mu[threadIdx.x] = mus[l * 48 + threadIdx.x];
                            is[threadIdx.x] = isgs[l * 48 + threadIdx.x]; }
    __syncthreads();
    float gi = 0.f, gj = 0.f, ge = 0.f, gtr = 0.f;
#pragma unroll
    for (int q = 0; q < 8; q++) {
        float df;
        df = sape[i * 8 + q] - mu[q];        gi  += -0.5f * df * df * is[q] * is[q];
        df = sape[j * 8 + q] - mu[8 + q];    gj  += -0.5f * df * df * is[8 + q] * is[8 + q];
        df = srpe[((size_t)i * Vv + j) * 8 + q] - mu[32 + q];
                                             ge  += -0.5f * df * df * is[32 + q] * is[32 + q];
        df = trpe[k * 8 + q] - mu[40 + q];   gtr += -0.5f * df * df * is[40 + q] * is[40 + q];
    }
    float m = mask[j * KV + k * Vv + i];
    g_Et[((size_t)l * Vv + j) * KV + k * Vv + i] = f2tf(m * expf(gi + gj + ge + gtr));
}

// ---------------- per-(l,b,t) scalars ----------------
__global__ void k_scalars(const float* __restrict__ tape, const float* __restrict__ mus,
                          const float* __restrict__ isgs) {
    int idx = blockIdx.x * blockDim.x + threadIdx.x;
    if (idx >= LL * BT) return;
    int l = idx / BT, bt = idx % BT;
    int b = bt / Tt, t = bt % Tt;
    const float* mu2 = mus + (l * 6 + 2) * 8; const float* is2 = isgs + (l * 6 + 2) * 8;
    const float* mu3 = mus + (l * 6 + 3) * 8; const float* is3 = isgs + (l * 6 + 3) * 8;
    float gti = 0.f;
    const float* tp = tape + (b * Tt + t) * 8;
#pragma unroll
    for (int q = 0; q < 8; q++) { float df = tp[q] - mu2[q]; gti += -0.5f * df * df * is2[q] * is2[q]; }
    g_ascal[idx] = expf(gti);
    for (int k = 0; k < 3; k++) {
        int s = t + k;
        float gtj = 0.f;
#pragma unroll
        for (int q = 0; q < 8; q++) {
            float e = (s < BETA) ? 0.f : tape[(b * Tt + (s - BETA)) * 8 + q];
            float df = e - mu3[q];
            gtj += -0.5f * df * df * is3[q] * is3[q];
        }
        g_wk[idx * 3 + k] = expf(gtj);
    }
}

// ---------------- SEP / TEP ----------------
__global__ void k_septep(const float* __restrict__ sape, const float* __restrict__ tape,
                         const float* __restrict__ sew, const float* __restrict__ tew,
                         const float* __restrict__ xpb) {
    int idx = blockIdx.x * blockDim.x + threadIdx.x;
    const int NSEP = LL * Vv * C2;
    const int NTEP = LL * BT * C2;
    if (idx < NSEP) {
        int l = idx / (Vv * C2);
        int v = (idx / C2) % Vv;
        int c2 = idx % C2;
        float acc = 0.f;
#pragma unroll
        for (int q = 0; q < 8; q++) acc += sape[v * 8 + q] * sew[(l * 8 + q) * C2 + c2];
        g_sep[idx] = acc;
    } else if (idx < NSEP + NTEP) {
        int jdx = idx - NSEP;
        int l = jdx / (BT * C2);
        int bt = (jdx / C2) % BT;
        int c2 = jdx % C2;
        float acc = xpb[l * C2 + c2];
#pragma unroll
        for (int q = 0; q < 8; q++) acc += tape[bt * 8 + q] * tew[(l * 8 + q) * C2 + c2];
        g_tep[jdx] = acc;
    }
}

// ============ pipelined MMA GEMMs (128x128 tiles, 2-stage cp.async) ============

// agg[bt][j][c] = ascal * sum_kv (wk[k]*E[j,kv]) * h[b,t+k,c,i]
__global__ __launch_bounds__(256) void k_agg_mma(int l) {
    extern __shared__ __align__(16) uint32_t smp[];
    uint32_t smb = smem_u32(smp);
    int tid = threadIdx.x;
    int wid = tid >> 5, lane = tid & 31;
    int wm = wid >> 2, wn = wid & 3;
    int bt = blockIdx.y, b = bt / Tt, t = bt % Tt;
    int j0 = blockIdx.x * 128;
    float acc[4][4][4];
    ACC_INIT(acc);
    const uint32_t* Abase = g_Et + ((size_t)l * Vv + j0) * KV;
    const uint32_t* Hbase = g_hTt + (size_t)(b * TPAD + t) * Cc * Vv;
    float wks[3] = { g_wk[(l * BT + bt) * 3 + 0], g_wk[(l * BT + bt) * 3 + 1],
                     g_wk[(l * BT + bt) * 3 + 2] };

    // prologue: chunk 0 -> stage 0
    fill_async(smb, Abase, KV, tid);
    fill_async(smb + TILE_BYTES, Hbase, Vv, tid);
    CP_COMMIT();
    const int NCH = 48;
    for (int ch = 0; ch < NCH; ch++) {
        int cur = ch & 1;
        if (ch + 1 < NCH) {
            int nc = ch + 1;
            int k = nc >> 4, i0 = (nc & 15) * 32;
            uint32_t so = (uint32_t)(cur ^ 1) * 2 * TILE_BYTES;
            fill_async(smb + so, Abase + nc * 32, KV, tid);
            fill_async(smb + so + TILE_BYTES,
                       Hbase + (size_t)k * Cc * Vv + i0, Vv, tid);
            CP_COMMIT();
            CP_WAIT1();
        } else {
            CP_WAIT0();
        }
        __syncthreads();
        const uint32_t* As = smp + (size_t)cur * 2 * (128 * PADK);
        const uint32_t* Bs = As + 128 * PADK;
        mma_chunk<true>(As, Bs, acc, wm, wn, lane, wks[ch >> 4]);
        __syncthreads();
    }
    float ascal = g_ascal[l * BT + bt];
    int g = lane >> 2, c = lane & 3;
#pragma unroll
    for (int mt = 0; mt < 4; mt++) {
#pragma unroll
        for (int nt = 0; nt < 4; nt++) {
            int row = wm * 64 + mt * 16 + g;
            int col = wn * 32 + nt * 8 + 2 * c;
            uint32_t* d0 = g_aggt + ((size_t)bt * Vv + j0 + row) * Cc + col;
            uint32_t* d1 = d0 + 8 * Cc;
            uint2 u0 = make_uint2(f2tf(acc[mt][nt][0] * ascal), f2tf(acc[mt][nt][1] * ascal));
            uint2 u1 = make_uint2(f2tf(acc[mt][nt][2] * ascal), f2tf(acc[mt][nt][3] * ascal));
            *(uint2*)d0 = u0;
            *(uint2*)d1 = u1;
        }
    }
}

// z = agg @ xproj_w[l]: M=BT*V, N=256, K=128
__global__ __launch_bounds__(256) void k_zgemm_mma(int l) {
    extern __shared__ __align__(16) uint32_t smp[];
    uint32_t smb = smem_u32(smp);
    int tid = threadIdx.x;
    int wid = tid >> 5, lane = tid & 31;
    int wm = wid >> 2, wn = wid & 3;
    int m0 = blockIdx.x * 128;
    int n0 = blockIdx.y * 128;
    float acc[4][4][4];
    ACC_INIT(acc);
    const uint32_t* Abase = g_aggt + (size_t)m0 * Cc;
    const uint32_t* Bbase = g_xwTt + (size_t)l * C2 * Cc + (size_t)n0 * Cc;

    fill_async(smb, Abase, Cc, tid);
    fill_async(smb + TILE_BYTES, Bbase, Cc, tid);
    CP_COMMIT();
    const int NCH = 4;
    for (int ch = 0; ch < NCH; ch++) {
        int cur = ch & 1;
        if (ch + 1 < NCH) {
            uint32_t so = (uint32_t)(cur ^ 1) * 2 * TILE_BYTES;
            fill_async(smb + so, Abase + (ch + 1) * 32, Cc, tid);
            fill_async(smb + so + TILE_BYTES, Bbase + (ch + 1) * 32, Cc, tid);
            CP_COMMIT();
            CP_WAIT1();
        } else {
            CP_WAIT0();
        }
        __syncthreads();
        const uint32_t* As = smp + (size_t)cur * 2 * (128 * PADK);
        const uint32_t* Bs = As + 128 * PADK;
        mma_chunk<false>(As, Bs, acc, wm, wn, lane, 1.f);
        __syncthreads();
    }
    int g = lane >> 2, c = lane & 3;
#pragma unroll
    for (int mt = 0; mt < 4; mt++) {
#pragma unroll
        for (int nt = 0; nt < 4; nt++) {
            int row = wm * 64 + mt * 16 + g;
            int col = wn * 32 + nt * 8 + 2 * c;
            float* d0 = g_z + (size_t)(m0 + row) * C2 + n0 + col;
            float* d1 = d0 + 8 * C2;
            *(float2*)d0 = make_float2(acc[mt][nt][0], acc[mt][nt][1]);
            *(float2*)d1 = make_float2(acc[mt][nt][2], acc[mt][nt][3]);
        }
    }
}

// GFS fc split-K: partial[ks][b][v][o] over chunks [ks*8, ks*8+8)
__global__ __launch_bounds__(256) void k_gfs_mma(int sidx) {
    extern __shared__ __align__(16) uint32_t smp[];
    uint32_t smb = smem_u32(smp);
    int tid = threadIdx.x;
    int wid = tid >> 5, lane = tid & 31;
    int wm = wid >> 2, wn = wid & 3;
    int v0 = blockIdx.x * 128;
    int b = blockIdx.y;
    int ks = blockIdx.z;
    float acc[4][4][4];
    ACC_INIT(acc);
    const uint32_t* fw = g_fwt + (size_t)sidx * Cc * KTC;

    auto asrc = [&](int gch) -> const uint32_t* {
        int t = gch >> 2, coff = (gch & 3) * 32;
        return g_ht + ((size_t)(b * TPAD + BETA + t) * Vv + v0) * Cc + coff;
    };
    int g0 = ks * 8;
    fill_async(smb, asrc(g0), Cc, tid);
    fill_async(smb + TILE_BYTES, fw + g0 * 32, KTC, tid);
    CP_COMMIT();
    const int NCH = 8;
    for (int ch = 0; ch < NCH; ch++) {
        int cur = ch & 1;
        if (ch + 1 < NCH) {
            int nc = g0 + ch + 1;
            uint32_t so = (uint32_t)(cur ^ 1) * 2 * TILE_BYTES;
            fill_async(smb + so, asrc(nc), Cc, tid);
            fill_async(smb + so + TILE_BYTES, fw + nc * 32, KTC, tid);
            CP_COMMIT();
            CP_WAIT1();
        } else {
            CP_WAIT0();
        }
        __syncthreads();
        const uint32_t* As = smp + (size_t)cur * 2 * (128 * PADK);
        const uint32_t* Bs = As + 128 * PADK;
        mma_chunk<false>(As, Bs, acc, wm, wn, lane, 1.f);
        __syncthreads();
    }
    int g = lane >> 2, c = lane & 3;
    float* part = g_spart + ((size_t)ks * Bb + b) * Vv * Cc;
#pragma unroll
    for (int mt = 0; mt < 4; mt++) {
#pragma unroll
        for (int nt = 0; nt < 4; nt++) {
            int row = wm * 64 + mt * 16 + g;
            int col = wn * 32 + nt * 8 + 2 * c;
            float* d0 = part + (size_t)(v0 + row) * Cc + col;
            float* d1 = d0 + 8 * Cc;
            *(float2*)d0 = make_float2(acc[mt][nt][0], acc[mt][nt][1]);
            *(float2*)d1 = make_float2(acc[mt][nt][2], acc[mt][nt][3]);
        }
    }
}

__global__ void k_gfs_red(const float* __restrict__ fb) {
    int idx = blockIdx.x * blockDim.x + threadIdx.x;
    if (idx >= Bb * Vv * Cc) return;
    int o = idx & 127;
    float s = fb[o];
#pragma unroll
    for (int ks = 0; ks < KSPL; ks++)
        s += g_spart[(size_t)ks * Bb * Vv * Cc + idx];
    g_s[idx] = s;
}

// head: g[b][p][v] = gb[p] + sum_o gw[p][o]*skipT[b][v][o]
__global__ __launch_bounds__(256) void k_headg_mma(const float* __restrict__ gb) {
    extern __shared__ __align__(16) uint32_t smp[];
    uint32_t smb = smem_u32(smp);
    int tid = threadIdx.x;
    int wid = tid >> 5, lane = tid & 31;
    int wm = wid >> 2, wn = wid & 3;
    int p0 = blockIdx.x * 128;
    int b = blockIdx.y >> 2;
    int n0 = (blockIdx.y & 3) * 128;
    float acc[4][4][4];
    ACC_INIT(acc);
    const uint32_t* Abase = g_gwt + (size_t)p0 * 512;
    const uint32_t* Bbase = g_skipTt + ((size_t)b * Vv + n0) * 512;

    fill_async(smb, Abase, 512, tid);
    fill_async(smb + TILE_BYTES, Bbase, 512, tid);
    CP_COMMIT();
    const int NCH = 16;
    for (int ch = 0; ch < NCH; ch++) {
        int cur = ch & 1;
        if (ch + 1 < NCH) {
            uint32_t so = (uint32_t)(cur ^ 1) * 2 * TILE_BYTES;
            fill_async(smb + so, Abase + (ch + 1) * 32, 512, tid);
            fill_async(smb + so + TILE_BYTES, Bbase + (ch + 1) * 32, 512, tid);
            CP_COMMIT();
            CP_WAIT1();
        } else {
            CP_WAIT0();
        }
        __syncthreads();
        const uint32_t* As = smp + (size_t)cur * 2 * (128 * PADK);
        const uint32_t* Bs = As + 128 * PADK;
        mma_chunk<false>(As, Bs, acc, wm, wn, lane, 1.f);
        __syncthreads();
    }
    int g = lane >> 2, c = lane & 3;
#pragma unroll
    for (int mt = 0; mt < 4; mt++) {
#pragma unroll
        for (int nt = 0; nt < 4; nt++) {
            int row = wm * 64 + mt * 16 + g;
            int col = wn * 32 + nt * 8 + 2 * c;
            float bi0 = gb[p0 + row], bi1 = gb[p0 + row + 8];
            float* d0 = g_g + ((size_t)b * 1024 + p0 + row) * Vv + n0 + col;
            float* d1 = d0 + 8 * Vv;
            *(float2*)d0 = make_float2(acc[mt][nt][0] + bi0, acc[mt][nt][1] + bi0);
            *(float2*)d1 = make_float2(acc[mt][nt][2] + bi1, acc[mt][nt][3] + bi1);
        }
    }
}

// ---- fused add + LayerNorm + GLU -> h (tf32, both layouts) ----
__global__ __launch_bounds__(256) void k_lnglu(int l, const float* __restrict__ lng,
                                               const float* __restrict__ lnb) {
    int w = threadIdx.x >> 5, lane = threadIdx.x & 31;
    int row = blockIdx.x * 8 + w;
    int bt = row >> 9, v = row & 511;
    int b = bt / Tt, t = bt % Tt;
    const float* zr = g_z + (size_t)row * C2;
    const float* sp = g_sep + ((size_t)l * Vv + v) * C2;
    const float* tp = g_tep + ((size_t)l * BT + bt) * C2;
    float val[8];
    float sum = 0.f;
#pragma unroll
    for (int q = 0; q < 8; q++) {
        int c2 = q * 32 + lane;
        val[q] = zr[c2] + sp[c2] + tp[c2];
        sum += val[q];
    }
#pragma unroll
    for (int o = 16; o; o >>= 1) sum += __shfl_xor_sync(0xffffffffu, sum, o);
    float mean = sum * (1.f / 256.f);
    float s2 = 0.f;
#pragma unroll
    for (int q = 0; q < 8; q++) { float df = val[q] - mean; s2 += df * df; }
#pragma unroll
    for (int o = 16; o; o >>= 1) s2 += __shfl_xor_sync(0xffffffffu, s2, o);
    float rstd = rsqrtf(s2 * (1.f / 256.f) + 1e-5f);
    float y[8];
#pragma unroll
    for (int q = 0; q < 8; q++) {
        int c2 = q * 32 + lane;
        y[q] = (val[q] - mean) * rstd * lng[l * C2 + c2] + lnb[l * C2 + c2];
    }
    size_t slab = (size_t)(b * TPAD + BETA + t);
    uint32_t* hp = g_ht + (slab * Vv + v) * Cc;
#pragma unroll
    for (int q = 0; q < 4; q++) {
        uint32_t hv = f2tf(y[q] * sigm(y[q + 4]));
        int c = q * 32 + lane;
        hp[c] = hv;
        g_hTt[(slab * Cc + c) * Vv + v] = hv;
    }
}

// ---- GFS GLU -> skipT tf32 ----
__global__ __launch_bounds__(128) void k_gfs_glu(int slot, const float* __restrict__ gw,
                                                 const float* __restrict__ gb) {
    int b = blockIdx.x >> 6;
    int v0 = (blockIdx.x & 63) * 8;
    __shared__ float s8[8][128];
    int o = threadIdx.x;
#pragma unroll
    for (int vi = 0; vi < 8; vi++)
        s8[vi][o] = g_s[((size_t)b * Vv + v0 + vi) * Cc + o];
    __syncthreads();
    float al[8], ar[8];
    float bl = gb[o], br = gb[o + 128];
#pragma unroll
    for (int vi = 0; vi < 8; vi++) { al[vi] = bl; ar[vi] = br; }
    const float* wl = gw + (size_t)o * 128;
    const float* wr = gw + (size_t)(o + 128) * 128;
    for (int c = 0; c < 128; c++) {
        float a = wl[c], bw = wr[c];
#pragma unroll
        for (int vi = 0; vi < 8; vi++) {
            float sv = s8[vi][c];
            al[vi] += a * sv;
            ar[vi] += bw * sv;
        }
    }
#pragma unroll
    for (int vi = 0; vi < 8; vi++)
        g_skipTt[((size_t)b * Vv + v0 + vi) * 512 + slot * 128 + o] =
            f2tf(al[vi] * sigm(ar[vi]));
}

// ---- output head (split q) ----
__global__ __launch_bounds__(512) void k_out_part(const float* __restrict__ ow) {
    __shared__ float ws[PP * 128];
    int b = blockIdx.x;
    int qs = blockIdx.y;
    int v = threadIdx.x;
    for (int i = v; i < PP * 128; i += 512) {
        int r = i >> 7, qq = i & 127;
        ws[i] = ow[r * 512 + qs * 128 + qq];
    }
    __syncthreads();
    float acc[PP];
#pragma unroll
    for (int r = 0; r < PP; r++) acc[r] = 0.f;
    const float* gB = g_g + (size_t)b * 1024 * Vv;
    for (int qq = 0; qq < 128; qq++) {
        int q = qs * 128 + qq;
        float gl = gB[(size_t)q * Vv + v];
        float gr = gB[(size_t)(512 + q) * Vv + v];
        float gate = gl * sigm(gr);
#pragma unroll
        for (int r = 0; r < PP; r++) acc[r] += ws[r * 128 + qq] * gate;
    }
#pragma unroll
    for (int r = 0; r < PP; r++)
        g_opart[(((size_t)qs * Bb + b) * PP + r) * Vv + v] = acc[r];
}

__global__ void k_out_red(const float* __restrict__ ob, float* __restrict__ out) {
    int idx = blockIdx.x * blockDim.x + threadIdx.x;
    if (idx >= Bb * PP * Vv) return;
    int r = (idx / Vv) % PP;
    float s = ob[r];
#pragma unroll
    for (int qs = 0; qs < QSPL; qs++)
        s += g_opart[(size_t)qs * Bb * PP * Vv + idx];
    out[idx] = s;
}

// ---------------- orchestration ----------------
extern "C" void kernel_launch(void* const* d_in, const int* in_sizes, int n_in,
                              void* d_out, int out_size) {
    const float* x          = (const float*)d_in[0];
    const float* sape       = (const float*)d_in[1];
    const float* tape       = (const float*)d_in[2];
    const float* srpe       = (const float*)d_in[3];
    const float* trpe       = (const float*)d_in[4];
    const float* range_mask = (const float*)d_in[7];
    const float* input_w    = (const float*)d_in[8];
    const float* input_b    = (const float*)d_in[9];
    const float* fs0_fc_w   = (const float*)d_in[10];
    const float* fs0_fc_b   = (const float*)d_in[11];
    const float* fs0_glu_w  = (const float*)d_in[12];
    const float* fs0_glu_b  = (const float*)d_in[13];
    const float* mus        = (const float*)d_in[14];
    const float* isgs       = (const float*)d_in[15];
    const float* xproj_w    = (const float*)d_in[16];
    const float* xproj_b    = (const float*)d_in[17];
    const float* seproj_w   = (const float*)d_in[18];
    const float* teproj_w   = (const float*)d_in[19];
    const float* ln_g       = (const float*)d_in[20];
    const float* ln_b       = (const float*)d_in[21];
    const float* fs_fc_w    = (const float*)d_in[22];
    const float* fs_fc_b    = (const float*)d_in[23];
    const float* fs_glu_w   = (const float*)d_in[24];
    const float* fs_glu_b   = (const float*)d_in[25];
    const float* glu_w      = (const float*)d_in[26];
    const float* glu_b      = (const float*)d_in[27];
    const float* out_w      = (const float*)d_in[28];
    const float* out_b      = (const float*)d_in[29];
    float* out = (float*)d_out;

    cudaFuncSetAttribute(k_agg_mma,   cudaFuncAttributeMaxDynamicSharedMemorySize, SMEM_PIPE);
    cudaFuncSetAttribute(k_zgemm_mma, cudaFuncAttributeMaxDynamicSharedMemorySize, SMEM_PIPE);
    cudaFuncSetAttribute(k_gfs_mma,   cudaFuncAttributeMaxDynamicSharedMemorySize, SMEM_PIPE);
    cudaFuncSetAttribute(k_headg_mma, cudaFuncAttributeMaxDynamicSharedMemorySize, SMEM_PIPE);

    // setup
    k_input<<<(Bb * TPAD * Vv * Cc) / 256, 256>>>(x, input_w, input_b);
    {
        int n = LL * C2 * Cc + 4 * Cc * KTC + 1024 * 512;
        k_cvtW<<<(n + 255) / 256, 256>>>(xproj_w, fs0_fc_w, fs_fc_w, glu_w);
    }
    k_buildE<<<LL * Vv * TSZ, 512>>>(sape, srpe, trpe, range_mask, mus, isgs);
    k_scalars<<<3, 96>>>(tape, mus, isgs);
    {
        int n = LL * Vv * C2 + LL * BT * C2;
        k_septep<<<(n + 255) / 256, 256>>>(sape, tape, seproj_w, teproj_w, xproj_b);
    }

    // skip 0
    k_gfs_mma<<<dim3(4, Bb, KSPL), 256, SMEM_PIPE>>>(0);
    k_gfs_red<<<(Bb * Vv * Cc + 255) / 256, 256>>>(fs0_fc_b);
    k_gfs_glu<<<Bb * 64, 128>>>(0, fs0_glu_w, fs0_glu_b);

    // layers
    for (int l = 0; l < LL; l++) {
        k_agg_mma<<<dim3(4, BT), 256, SMEM_PIPE>>>(l);
        k_zgemm_mma<<<dim3(BT * Vv / 128, 2), 256, SMEM_PIPE>>>(l);
        k_lnglu<<<BT * Vv / 8, 256>>>(l, ln_g, ln_b);
        k_gfs_mma<<<dim3(4, Bb, KSPL), 256, SMEM_PIPE>>>(l + 1);
        k_gfs_red<<<(Bb * Vv * Cc + 255) / 256, 256>>>(fs_fc_b + l * Cc);
        k_gfs_glu<<<Bb * 64, 128>>>(l + 1, fs_glu_w + (size_t)l * 2 * Cc * Cc,
                                    fs_glu_b + l * 2 * Cc);
    }

    // head
    k_headg_mma<<<dim3(8, 32), 256, SMEM_PIPE>>>(glu_b);
    k_out_part<<<dim3(Bb, QSPL), 512>>>(out_w);
    k_out_red<<<(Bb * PP * Vv + 255) / 256, 256>>>(out_b, out);
}

// round 6
// speedup vs baseline: 3.6448x; 1.1052x over previous
#include <cuda_runtime.h>
#include <math.h>
#include <cstdint>

// ---------------- problem constants ----------------
#define Bb   8
#define Tt   12
#define Vv   512
#define Cc   128
#define TSZ  3
#define LL   3
#define PP   12
#define BETA 2
#define TPAD (Tt + BETA)   // 14
#define C2   256
#define KV   (TSZ * Vv)    // 1536
#define KTC  (Tt * Cc)     // 1536
#define BT   (Bb * Tt)     // 96
#define PADK 36
#define KSPL 6             // gfs split-K
#define QSPL 4             // out split-q

#define TILE_BYTES (128 * PADK * 4)        // 18432
#define SMEM_PIPE  (4 * TILE_BYTES)        // 73728 (2 stages x A,B)

// ---------------- device scratch (static; no runtime alloc) ----------------
__device__ __align__(16) uint32_t g_ht [Bb * TPAD * Vv * Cc];   // tf32 h [b][tp][v][c]
__device__ __align__(16) uint32_t g_hTt[Bb * TPAD * Cc * Vv];   // tf32 h [b][tp][c][v]
__device__ __align__(16) uint32_t g_Et [LL * Vv * KV];          // tf32 E
__device__ __align__(16) uint32_t g_aggt[BT * Vv * Cc];         // tf32 agg
__device__ __align__(16) float    g_z[BT * Vv * C2];
__device__ __align__(16) float    g_s[Bb * Vv * Cc];
__device__ __align__(16) float    g_spart[KSPL * Bb * Vv * Cc];
__device__ __align__(16) uint32_t g_skipTt[Bb * Vv * 512];      // tf32 [b][v][o]
__device__ __align__(16) float    g_g[Bb * 1024 * Vv];
__device__ __align__(16) float    g_sep[LL * Vv * C2];
__device__ __align__(16) float    g_tep[LL * BT * C2];
__device__ __align__(16) uint32_t g_xwTt[LL * C2 * Cc];         // tf32 [l][n][k]
__device__ __align__(16) uint32_t g_fwt[4 * Cc * KTC];          // tf32 [s][o][tc]
__device__ __align__(16) uint32_t g_gwt[1024 * 512];            // tf32 glu_w
__device__ __align__(16) float    g_opart[QSPL * Bb * PP * Vv];

__device__ __forceinline__ float sigm(float x) { return 1.f / (1.f + expf(-x)); }
__device__ __forceinline__ uint32_t f2tf(float v) {
    uint32_t r;
    asm("cvt.rna.tf32.f32 %0, %1;" : "=r"(r) : "f"(v));
    return r;
}
__device__ __forceinline__ uint32_t smem_u32(const void* p) {
    uint32_t a;
    asm("{ .reg .u64 t; cvta.to.shared.u64 t, %1; cvt.u32.u64 %0, t; }" : "=r"(a) : "l"(p));
    return a;
}
__device__ __forceinline__ void cpa16(uint32_t dst, const void* src) {
    asm volatile("cp.async.cg.shared.global [%0], [%1], 16;" :: "r"(dst), "l"(src));
}
#define CP_COMMIT() asm volatile("cp.async.commit_group;" ::: "memory")
#define CP_WAIT0()  asm volatile("cp.async.wait_group 0;" ::: "memory")
#define CP_WAIT1()  asm volatile("cp.async.wait_group 1;" ::: "memory")

// Fill a 128x32 tf32 tile into smem stage (byte addr smdst), 16B cp.async, 128 thr.
__device__ __forceinline__ void fill_async(uint32_t smdst, const uint32_t* __restrict__ src,
                                           int rstride, int tid) {
#pragma unroll
    for (int q = 0; q < 8; q++) {
        int idx = q * 128 + tid;
        int r = idx >> 3;
        int c4 = (idx & 7) << 2;
        cpa16(smdst + (uint32_t)(r * PADK + c4) * 4, src + (size_t)r * rstride + c4);
    }
}

// One K=32 chunk of 128x128 MMA. 4 warps: wm=wid>>1, wn=wid&1; warp tile 64x64.
template <bool SCALE>
__device__ __forceinline__ void mma_chunk(const uint32_t* As, const uint32_t* Bs,
                                          float acc[4][8][4], int wm, int wn, int lane,
                                          float w) {
    int g = lane >> 2, c = lane & 3;
#pragma unroll
    for (int kk = 0; kk < 4; kk++) {
        uint32_t a[4][4];
#pragma unroll
        for (int mt = 0; mt < 4; mt++) {
            const uint32_t* ap = As + (wm * 64 + mt * 16 + g) * PADK + kk * 8 + c;
            a[mt][0] = ap[0];
            a[mt][1] = ap[8 * PADK];
            a[mt][2] = ap[4];
            a[mt][3] = ap[8 * PADK + 4];
            if (SCALE) {
#pragma unroll
                for (int e = 0; e < 4; e++)
                    a[mt][e] = f2tf(__uint_as_float(a[mt][e]) * w);
            }
        }
#pragma unroll
        for (int nt = 0; nt < 8; nt++) {
            const uint32_t* bp = Bs + (wn * 64 + nt * 8 + g) * PADK + kk * 8 + c;
            uint32_t b0 = bp[0], b1 = bp[4];
#pragma unroll
            for (int mt = 0; mt < 4; mt++) {
                asm volatile(
                    "mma.sync.aligned.m16n8k8.row.col.f32.tf32.tf32.f32 "
                    "{%0,%1,%2,%3}, {%4,%5,%6,%7}, {%8,%9}, {%0,%1,%2,%3};"
                    : "+f"(acc[mt][nt][0]), "+f"(acc[mt][nt][1]),
                      "+f"(acc[mt][nt][2]), "+f"(acc[mt][nt][3])
                    : "r"(a[mt][0]), "r"(a[mt][1]), "r"(a[mt][2]), "r"(a[mt][3]),
                      "r"(b0), "r"(b1));
            }
        }
    }
}

#define ACC_INIT(acc) \
    _Pragma("unroll") for (int _m = 0; _m < 4; _m++) \
    _Pragma("unroll") for (int _n = 0; _n < 8; _n++) \
    _Pragma("unroll") for (int _e = 0; _e < 4; _e++) acc[_m][_n][_e] = 0.f;

// ---------------- h = [zeros ; x@input_w + input_b] (tf32) ----------------
__global__ void k_input(const float* __restrict__ x, const float* __restrict__ iw,
                        const float* __restrict__ ib) {
    int idx = blockIdx.x * blockDim.x + threadIdx.x;
    if (idx >= Bb * TPAD * Vv * Cc) return;
    int c = idx & 127;
    int rest = idx >> 7;
    int v = rest & 511;
    int bt = rest >> 9;
    int tp = bt % TPAD;
    int b  = bt / TPAD;
    float val = 0.f;
    if (tp >= BETA) {
        float xv = x[(b * Tt + (tp - BETA)) * Vv + v];
        val = xv * iw[c] + ib[c];
    }
    g_ht[idx] = f2tf(val);
}

// ---------------- h [v][c] -> hT [c][v], coalesced 32x32 tiles ----------------
__global__ void k_transp(int active) {
    __shared__ uint32_t tile[32][33];
    int z = blockIdx.z;
    int slab = active ? ((z / Tt) * TPAD + BETA + (z % Tt)) : z;
    int c0 = blockIdx.x * 32, v0 = blockIdx.y * 32;
    int tx = threadIdx.x, ty = threadIdx.y;    // 32 x 8
    const uint32_t* src = g_ht + (size_t)slab * Vv * Cc;
#pragma unroll
    for (int r = 0; r < 4; r++)
        tile[ty + 8 * r][tx] = src[(size_t)(v0 + ty + 8 * r) * Cc + c0 + tx];
    __syncthreads();
    uint32_t* dst = g_hTt + (size_t)slab * Cc * Vv;
#pragma unroll
    for (int r = 0; r < 4; r++)
        dst[(size_t)(c0 + ty + 8 * r) * Vv + v0 + tx] = tile[tx][ty + 8 * r];
}

// ---------------- weight conversions (once) ----------------
__global__ void k_cvtW(const float* __restrict__ xw, const float* __restrict__ fs0,
                       const float* __restrict__ fsl, const float* __restrict__ gw) {
    int idx = blockIdx.x * blockDim.x + threadIdx.x;
    const int N1 = LL * C2 * Cc;
    const int N2 = 4 * Cc * KTC;
    const int N3 = 1024 * 512;
    if (idx < N1) {
        int l = idx / (C2 * Cc);
        int n = (idx / Cc) % C2;
        int k = idx % Cc;
        g_xwTt[idx] = f2tf(xw[((size_t)l * Cc + k) * C2 + n]);
    } else if (idx < N1 + N2) {
        int j = idx - N1;
        int s = j / (Cc * KTC);
        int r = j % (Cc * KTC);
        float v = (s == 0) ? fs0[r] : fsl[(size_t)(s - 1) * Cc * KTC + r];
        g_fwt[j] = f2tf(v);
    } else if (idx < N1 + N2 + N3) {
        int j = idx - N1 - N2;
        g_gwt[j] = f2tf(gw[j]);
    }
}

// ---------------- E (tf32) ----------------
__global__ void k_buildE(const float* __restrict__ sape, const float* __restrict__ srpe,
                         const float* __restrict__ trpe, const float* __restrict__ mask,
                         const float* __restrict__ mus, const float* __restrict__ isgs) {
    int blk = blockIdx.x;
    int l = blk / (Vv * 3);
    int rem = blk % (Vv * 3);
    int j = rem / 3, k = rem % 3;
    int i = threadIdx.x;
    __shared__ float mu[48], is[48];
    if (threadIdx.x < 48) { mu[threadIdx.x] = mus[l * 48 + threadIdx.x];
                            is[threadIdx.x] = isgs[l * 48 + threadIdx.x]; }
    __syncthreads();
    float gi = 0.f, gj = 0.f, ge = 0.f, gtr = 0.f;
#pragma unroll
    for (int q = 0; q < 8; q++) {
        float df;
        df = sape[i * 8 + q] - mu[q];        gi  += -0.5f * df * df * is[q] * is[q];
        df = sape[j * 8 + q] - mu[8 + q];    gj  += -0.5f * df * df * is[8 + q] * is[8 + q];
        df = srpe[((size_t)i * Vv + j) * 8 + q] - mu[32 + q];
                                             ge  += -0.5f * df * df * is[32 + q] * is[32 + q];
        df = trpe[k * 8 + q] - mu[40 + q];   gtr += -0.5f * df * df * is[40 + q] * is[40 + q];
    }
    float m = mask[j * KV + k * Vv + i];
    g_Et[((size_t)l * Vv + j) * KV + k * Vv + i] = f2tf(m * expf(gi + gj + ge + gtr));
}

// ---------------- SEP / TEP ----------------
__global__ void k_septep(const float* __restrict__ sape, const float* __restrict__ tape,
                         const float* __restrict__ sew, const float* __restrict__ tew,
                         const float* __restrict__ xpb) {
    int idx = blockIdx.x * blockDim.x + threadIdx.x;
    const int NSEP = LL * Vv * C2;
    const int NTEP = LL * BT * C2;
    if (idx < NSEP) {
        int l = idx / (Vv * C2);
        int v = (idx / C2) % Vv;
        int c2 = idx % C2;
        float acc = 0.f;
#pragma unroll
        for (int q = 0; q < 8; q++) acc += sape[v * 8 + q] * sew[(l * 8 + q) * C2 + c2];
        g_sep[idx] = acc;
    } else if (idx < NSEP + NTEP) {
        int jdx = idx - NSEP;
        int l = jdx / (BT * C2);
        int bt = (jdx / C2) % BT;
        int c2 = jdx % C2;
        float acc = xpb[l * C2 + c2];
#pragma unroll
        for (int q = 0; q < 8; q++) acc += tape[bt * 8 + q] * tew[(l * 8 + q) * C2 + c2];
        g_tep[jdx] = acc;
    }
}

// ============ pipelined MMA GEMMs (128x128 CTA tile, 4 warps, 2-stage) ============

// agg[bt][j][c] = ascal * sum_kv (wk[k]*E[j,kv]) * h[b,t+k,c,i]
__global__ __launch_bounds__(128) void k_agg_mma(int l, const float* __restrict__ tape,
                                                 const float* __restrict__ mus,
                                                 const float* __restrict__ isgs) {
    extern __shared__ __align__(16) uint32_t smp[];
    uint32_t smb = smem_u32(smp);
    int tid = threadIdx.x;
    int wid = tid >> 5, lane = tid & 31;
    int wm = wid >> 1, wn = wid & 1;
    int bt = blockIdx.y, b = bt / Tt, t = bt % Tt;
    int j0 = blockIdx.x * 128;
    float acc[4][8][4];
    ACC_INIT(acc);

    // inline per-(l,bt) scalars: ascal = exp(gti), wks[k] = exp(gtj)
    float wks[3], ascal;
    {
        const float* mu2 = mus + (l * 6 + 2) * 8; const float* is2 = isgs + (l * 6 + 2) * 8;
        const float* mu3 = mus + (l * 6 + 3) * 8; const float* is3 = isgs + (l * 6 + 3) * 8;
        const float* tp = tape + bt * 8;
        float gti = 0.f;
#pragma unroll
        for (int q = 0; q < 8; q++) { float df = tp[q] - mu2[q]; gti += -0.5f * df * df * is2[q] * is2[q]; }
        ascal = expf(gti);
#pragma unroll
        for (int k = 0; k < 3; k++) {
            int s = t + k;
            float gtj = 0.f;
#pragma unroll
            for (int q = 0; q < 8; q++) {
                float e = (s < BETA) ? 0.f : tape[(b * Tt + (s - BETA)) * 8 + q];
                float df = e - mu3[q];
                gtj += -0.5f * df * df * is3[q] * is3[q];
            }
            wks[k] = expf(gtj);
        }
    }

    const uint32_t* Abase = g_Et + ((size_t)l * Vv + j0) * KV;
    const uint32_t* Hbase = g_hTt + (size_t)(b * TPAD + t) * Cc * Vv;

    fill_async(smb, Abase, KV, tid);
    fill_async(smb + TILE_BYTES, Hbase, Vv, tid);
    CP_COMMIT();
    const int NCH = 48;
    for (int ch = 0; ch < NCH; ch++) {
        int cur = ch & 1;
        if (ch + 1 < NCH) {
            int nc = ch + 1;
            int k = nc >> 4, i0 = (nc & 15) * 32;
            uint32_t so = (uint32_t)(cur ^ 1) * 2 * TILE_BYTES;
            fill_async(smb + so, Abase + nc * 32, KV, tid);
            fill_async(smb + so + TILE_BYTES, Hbase + (size_t)k * Cc * Vv + i0, Vv, tid);
            CP_COMMIT();
            CP_WAIT1();
        } else {
            CP_WAIT0();
        }
        __syncthreads();
        const uint32_t* As = smp + (size_t)cur * 2 * (128 * PADK);
        const uint32_t* Bs = As + 128 * PADK;
        mma_chunk<true>(As, Bs, acc, wm, wn, lane, wks[ch >> 4]);
        __syncthreads();
    }
    int g = lane >> 2, c = lane & 3;
#pragma unroll
    for (int mt = 0; mt < 4; mt++) {
#pragma unroll
        for (int nt = 0; nt < 8; nt++) {
            int row = wm * 64 + mt * 16 + g;
            int col = wn * 64 + nt * 8 + 2 * c;
            uint32_t* d0 = g_aggt + ((size_t)bt * Vv + j0 + row) * Cc + col;
            uint32_t* d1 = d0 + 8 * Cc;
            *(uint2*)d0 = make_uint2(f2tf(acc[mt][nt][0] * ascal), f2tf(acc[mt][nt][1] * ascal));
            *(uint2*)d1 = make_uint2(f2tf(acc[mt][nt][2] * ascal), f2tf(acc[mt][nt][3] * ascal));
        }
    }
}

// z = agg @ xproj_w[l]: M=BT*V, N=256, K=128
__global__ __launch_bounds__(128) void k_zgemm_mma(int l) {
    extern __shared__ __align__(16) uint32_t smp[];
    uint32_t smb = smem_u32(smp);
    int tid = threadIdx.x;
    int wid = tid >> 5, lane = tid & 31;
    int wm = wid >> 1, wn = wid & 1;
    int m0 = blockIdx.x * 128;
    int n0 = blockIdx.y * 128;
    float acc[4][8][4];
    ACC_INIT(acc);
    const uint32_t* Abase = g_aggt + (size_t)m0 * Cc;
    const uint32_t* Bbase = g_xwTt + (size_t)l * C2 * Cc + (size_t)n0 * Cc;

    fill_async(smb, Abase, Cc, tid);
    fill_async(smb + TILE_BYTES, Bbase, Cc, tid);
    CP_COMMIT();
    const int NCH = 4;
    for (int ch = 0; ch < NCH; ch++) {
        int cur = ch & 1;
        if (ch + 1 < NCH) {
            uint32_t so = (uint32_t)(cur ^ 1) * 2 * TILE_BYTES;
            fill_async(smb + so, Abase + (ch + 1) * 32, Cc, tid);
            fill_async(smb + so + TILE_BYTES, Bbase + (ch + 1) * 32, Cc, tid);
            CP_COMMIT();
            CP_WAIT1();
        } else {
            CP_WAIT0();
        }
        __syncthreads();
        const uint32_t* As = smp + (size_t)cur * 2 * (128 * PADK);
        const uint32_t* Bs = As + 128 * PADK;
        mma_chunk<false>(As, Bs, acc, wm, wn, lane, 1.f);
        __syncthreads();
    }
    int g = lane >> 2, c = lane & 3;
#pragma unroll
    for (int mt = 0; mt < 4; mt++) {
#pragma unroll
        for (int nt = 0; nt < 8; nt++) {
            int row = wm * 64 + mt * 16 + g;
            int col = wn * 64 + nt * 8 + 2 * c;
            float* d0 = g_z + (size_t)(m0 + row) * C2 + n0 + col;
            float* d1 = d0 + 8 * C2;
            *(float2*)d0 = make_float2(acc[mt][nt][0], acc[mt][nt][1]);
            *(float2*)d1 = make_float2(acc[mt][nt][2], acc[mt][nt][3]);
        }
    }
}

// GFS fc split-K: partial[ks][b][v][o] over chunks [ks*8, ks*8+8)
__global__ __launch_bounds__(128) void k_gfs_mma(int sidx) {
    extern __shared__ __align__(16) uint32_t smp[];
    uint32_t smb = smem_u32(smp);
    int tid = threadIdx.x;
    int wid = tid >> 5, lane = tid & 31;
    int wm = wid >> 1, wn = wid & 1;
    int v0 = blockIdx.x * 128;
    int b = blockIdx.y;
    int ks = blockIdx.z;
    float acc[4][8][4];
    ACC_INIT(acc);
    const uint32_t* fw = g_fwt + (size_t)sidx * Cc * KTC;

    auto asrc = [&](int gch) -> const uint32_t* {
        int t = gch >> 2, coff = (gch & 3) * 32;
        return g_ht + ((size_t)(b * TPAD + BETA + t) * Vv + v0) * Cc + coff;
    };
    int g0 = ks * 8;
    fill_async(smb, asrc(g0), Cc, tid);
    fill_async(smb + TILE_BYTES, fw + g0 * 32, KTC, tid);
    CP_COMMIT();
    const int NCH = 8;
    for (int ch = 0; ch < NCH; ch++) {
        int cur = ch & 1;
        if (ch + 1 < NCH) {
            int nc = g0 + ch + 1;
            uint32_t so = (uint32_t)(cur ^ 1) * 2 * TILE_BYTES;
            fill_async(smb + so, asrc(nc), Cc, tid);
            fill_async(smb + so + TILE_BYTES, fw + nc * 32, KTC, tid);
            CP_COMMIT();
            CP_WAIT1();
        } else {
            CP_WAIT0();
        }
        __syncthreads();
        const uint32_t* As = smp + (size_t)cur * 2 * (128 * PADK);
        const uint32_t* Bs = As + 128 * PADK;
        mma_chunk<false>(As, Bs, acc, wm, wn, lane, 1.f);
        __syncthreads();
    }
    int g = lane >> 2, c = lane & 3;
    float* part = g_spart + ((size_t)ks * Bb + b) * Vv * Cc;
#pragma unroll
    for (int mt = 0; mt < 4; mt++) {
#pragma unroll
        for (int nt = 0; nt < 8; nt++) {
            int row = wm * 64 + mt * 16 + g;
            int col = wn * 64 + nt * 8 + 2 * c;
            float* d0 = part + (size_t)(v0 + row) * Cc + col;
            float* d1 = d0 + 8 * Cc;
            *(float2*)d0 = make_float2(acc[mt][nt][0], acc[mt][nt][1]);
            *(float2*)d1 = make_float2(acc[mt][nt][2], acc[mt][nt][3]);
        }
    }
}

__global__ void k_gfs_red(const float* __restrict__ fb) {
    int idx = blockIdx.x * blockDim.x + threadIdx.x;
    if (idx >= Bb * Vv * Cc) return;
    int o = idx & 127;
    float s = fb[o];
#pragma unroll
    for (int ks = 0; ks < KSPL; ks++)
        s += g_spart[(size_t)ks * Bb * Vv * Cc + idx];
    g_s[idx] = s;
}

// head: g[b][p][v] = gb[p] + sum_o gw[p][o]*skipT[b][v][o]
__global__ __launch_bounds__(128) void k_headg_mma(const float* __restrict__ gb) {
    extern __shared__ __align__(16) uint32_t smp[];
    uint32_t smb = smem_u32(smp);
    int tid = threadIdx.x;
    int wid = tid >> 5, lane = tid & 31;
    int wm = wid >> 1, wn = wid & 1;
    int p0 = blockIdx.x * 128;
    int b = blockIdx.y >> 2;
    int n0 = (blockIdx.y & 3) * 128;
    float acc[4][8][4];
    ACC_INIT(acc);
    const uint32_t* Abase = g_gwt + (size_t)p0 * 512;
    const uint32_t* Bbase = g_skipTt + ((size_t)b * Vv + n0) * 512;

    fill_async(smb, Abase, 512, tid);
    fill_async(smb + TILE_BYTES, Bbase, 512, tid);
    CP_COMMIT();
    const int NCH = 16;
    for (int ch = 0; ch < NCH; ch++) {
        int cur = ch & 1;
        if (ch + 1 < NCH) {
            uint32_t so = (uint32_t)(cur ^ 1) * 2 * TILE_BYTES;
            fill_async(smb + so, Abase + (ch + 1) * 32, 512, tid);
            fill_async(smb + so + TILE_BYTES, Bbase + (ch + 1) * 32, 512, tid);
            CP_COMMIT();
            CP_WAIT1();
        } else {
            CP_WAIT0();
        }
        __syncthreads();
        const uint32_t* As = smp + (size_t)cur * 2 * (128 * PADK);
        const uint32_t* Bs = As + 128 * PADK;
        mma_chunk<false>(As, Bs, acc, wm, wn, lane, 1.f);
        __syncthreads();
    }
    int g = lane >> 2, c = lane & 3;
#pragma unroll
    for (int mt = 0; mt < 4; mt++) {
#pragma unroll
        for (int nt = 0; nt < 8; nt++) {
            int row = wm * 64 + mt * 16 + g;
            int col = wn * 64 + nt * 8 + 2 * c;
            float bi0 = gb[p0 + row], bi1 = gb[p0 + row + 8];
            float* d0 = g_g + ((size_t)b * 1024 + p0 + row) * Vv + n0 + col;
            float* d1 = d0 + 8 * Vv;
            *(float2*)d0 = make_float2(acc[mt][nt][0] + bi0, acc[mt][nt][1] + bi0);
            *(float2*)d1 = make_float2(acc[mt][nt][2] + bi1, acc[mt][nt][3] + bi1);
        }
    }
}

// ---- fused add + LayerNorm + GLU -> h (tf32) ----
__global__ __launch_bounds__(256) void k_lnglu(int l, const float* __restrict__ lng,
                                               const float* __restrict__ lnb) {
    int w = threadIdx.x >> 5, lane = threadIdx.x & 31;
    int row = blockIdx.x * 8 + w;
    int bt = row >> 9, v = row & 511;
    int b = bt / Tt, t = bt % Tt;
    const float* zr = g_z + (size_t)row * C2;
    const float* sp = g_sep + ((size_t)l * Vv + v) * C2;
    const float* tp = g_tep + ((size_t)l * BT + bt) * C2;
    float val[8];
    float sum = 0.f;
#pragma unroll
    for (int q = 0; q < 8; q++) {
        int c2 = q * 32 + lane;
        val[q] = zr[c2] + sp[c2] + tp[c2];
        sum += val[q];
    }
#pragma unroll
    for (int o = 16; o; o >>= 1) sum += __shfl_xor_sync(0xffffffffu, sum, o);
    float mean = sum * (1.f / 256.f);
    float s2 = 0.f;
#pragma unroll
    for (int q = 0; q < 8; q++) { float df = val[q] - mean; s2 += df * df; }
#pragma unroll
    for (int o = 16; o; o >>= 1) s2 += __shfl_xor_sync(0xffffffffu, s2, o);
    float rstd = rsqrtf(s2 * (1.f / 256.f) + 1e-5f);
    float y[8];
#pragma unroll
    for (int q = 0; q < 8; q++) {
        int c2 = q * 32 + lane;
        y[q] = (val[q] - mean) * rstd * lng[l * C2 + c2] + lnb[l * C2 + c2];
    }
    size_t slab = (size_t)(b * TPAD + BETA + t);
    uint32_t* hp = g_ht + (slab * Vv + v) * Cc;
#pragma unroll
    for (int q = 0; q < 4; q++)
        hp[q * 32 + lane] = f2tf(y[q] * sigm(y[q + 4]));
}

// ---- GFS GLU -> skipT tf32 ----
__global__ __launch_bounds__(128) void k_gfs_glu(int slot, const float* __restrict__ gw,
                                                 const float* __restrict__ gb) {
    int b = blockIdx.x >> 6;
    int v0 = (blockIdx.x & 63) * 8;
    __shared__ float s8[8][128];
    int o = threadIdx.x;
#pragma unroll
    for (int vi = 0; vi < 8; vi++)
        s8[vi][o] = g_s[((size_t)b * Vv + v0 + vi) * Cc + o];
    __syncthreads();
    float al[8], ar[8];
    float bl = gb[o], br = gb[o + 128];
#pragma unroll
    for (int vi = 0; vi < 8; vi++) { al[vi] = bl; ar[vi] = br; }
    const float* wl = gw + (size_t)o * 128;
    const float* wr = gw + (size_t)(o + 128) * 128;
    for (int c = 0; c < 128; c++) {
        float a = wl[c], bw = wr[c];
#pragma unroll
        for (int vi = 0; vi < 8; vi++) {
            float sv = s8[vi][c];
            al[vi] += a * sv;
            ar[vi] += bw * sv;
        }
    }
#pragma unroll
    for (int vi = 0; vi < 8; vi++)
        g_skipTt[((size_t)b * Vv + v0 + vi) * 512 + slot * 128 + o] =
            f2tf(al[vi] * sigm(ar[vi]));
}

// ---- output head (split q) ----
__global__ __launch_bounds__(512) void k_out_part(const float* __restrict__ ow) {
    __shared__ float ws[PP * 128];
    int b = blockIdx.x;
    int qs = blockIdx.y;
    int v = threadIdx.x;
    for (int i = v; i < PP * 128; i += 512) {
        int r = i >> 7, qq = i & 127;
        ws[i] = ow[r * 512 + qs * 128 + qq];
    }
    __syncthreads();
    float acc[PP];
#pragma unroll
    for (int r = 0; r < PP; r++) acc[r] = 0.f;
    const float* gB = g_g + (size_t)b * 1024 * Vv;
    for (int qq = 0; qq < 128; qq++) {
        int q = qs * 128 + qq;
        float gl = gB[(size_t)q * Vv + v];
        float gr = gB[(size_t)(512 + q) * Vv + v];
        float gate = gl * sigm(gr);
#pragma unroll
        for (int r = 0; r < PP; r++) acc[r] += ws[r * 128 + qq] * gate;
    }
#pragma unroll
    for (int r = 0; r < PP; r++)
        g_opart[(((size_t)qs * Bb + b) * PP + r) * Vv + v] = acc[r];
}

__global__ void k_out_red(const float* __restrict__ ob, float* __restrict__ out) {
    int idx = blockIdx.x * blockDim.x + threadIdx.x;
    if (idx >= Bb * PP * Vv) return;
    int r = (idx / Vv) % PP;
    float s = ob[r];
#pragma unroll
    for (int qs = 0; qs < QSPL; qs++)
        s += g_opart[(size_t)qs * Bb * PP * Vv + idx];
    out[idx] = s;
}

// ---------------- orchestration ----------------
extern "C" void kernel_launch(void* const* d_in, const int* in_sizes, int n_in,
                              void* d_out, int out_size) {
    const float* x          = (const float*)d_in[0];
    const float* sape       = (const float*)d_in[1];
    const float* tape       = (const float*)d_in[2];
    const float* srpe       = (const float*)d_in[3];
    const float* trpe       = (const float*)d_in[4];
    const float* range_mask = (const float*)d_in[7];
    const float* input_w    = (const float*)d_in[8];
    const float* input_b    = (const float*)d_in[9];
    const float* fs0_fc_w   = (const float*)d_in[10];
    const float* fs0_fc_b   = (const float*)d_in[11];
    const float* fs0_glu_w  = (const float*)d_in[12];
    const float* fs0_glu_b  = (const float*)d_in[13];
    const float* mus        = (const float*)d_in[14];
    const float* isgs       = (const float*)d_in[15];
    const float* xproj_w    = (const float*)d_in[16];
    const float* xproj_b    = (const float*)d_in[17];
    const float* seproj_w   = (const float*)d_in[18];
    const float* teproj_w   = (const float*)d_in[19];
    const float* ln_g       = (const float*)d_in[20];
    const float* ln_b       = (const float*)d_in[21];
    const float* fs_fc_w    = (const float*)d_in[22];
    const float* fs_fc_b    = (const float*)d_in[23];
    const float* fs_glu_w   = (const float*)d_in[24];
    const float* fs_glu_b   = (const float*)d_in[25];
    const float* glu_w      = (const float*)d_in[26];
    const float* glu_b      = (const float*)d_in[27];
    const float* out_w      = (const float*)d_in[28];
    const float* out_b      = (const float*)d_in[29];
    float* out = (float*)d_out;

    cudaFuncSetAttribute(k_agg_mma,   cudaFuncAttributeMaxDynamicSharedMemorySize, SMEM_PIPE);
    cudaFuncSetAttribute(k_zgemm_mma, cudaFuncAttributeMaxDynamicSharedMemorySize, SMEM_PIPE);
    cudaFuncSetAttribute(k_gfs_mma,   cudaFuncAttributeMaxDynamicSharedMemorySize, SMEM_PIPE);
    cudaFuncSetAttribute(k_headg_mma, cudaFuncAttributeMaxDynamicSharedMemorySize, SMEM_PIPE);

    // 1..3: prerequisites for agg(0); 4: agg(0) (the launch ncu captures)
    k_input<<<(Bb * TPAD * Vv * Cc) / 256, 256>>>(x, input_w, input_b);
    k_transp<<<dim3(4, 16, Bb * TPAD), dim3(32, 8)>>>(0);
    k_buildE<<<LL * Vv * TSZ, 512>>>(sape, srpe, trpe, range_mask, mus, isgs);
    k_agg_mma<<<dim3(4, BT), 128, SMEM_PIPE>>>(0, tape, mus, isgs);

    // remaining setup
    {
        int n = LL * C2 * Cc + 4 * Cc * KTC + 1024 * 512;
        k_cvtW<<<(n + 255) / 256, 256>>>(xproj_w, fs0_fc_w, fs_fc_w, glu_w);
    }
    {
        int n = LL * Vv * C2 + LL * BT * C2;
        k_septep<<<(n + 255) / 256, 256>>>(sape, tape, seproj_w, teproj_w, xproj_b);
    }

    // skip slot 0 (uses pre-layer h; must precede lnglu(0))
    k_gfs_mma<<<dim3(4, Bb, KSPL), 128, SMEM_PIPE>>>(0);
    k_gfs_red<<<(Bb * Vv * Cc + 255) / 256, 256>>>(fs0_fc_b);
    k_gfs_glu<<<Bb * 64, 128>>>(0, fs0_glu_w, fs0_glu_b);

    for (int l = 0; l < LL; l++) {
        if (l > 0) k_agg_mma<<<dim3(4, BT), 128, SMEM_PIPE>>>(l, tape, mus, isgs);
        k_zgemm_mma<<<dim3(BT * Vv / 128, 2), 128, SMEM_PIPE>>>(l);
        k_lnglu<<<BT * Vv / 8, 256>>>(l, ln_g, ln_b);
        if (l < LL - 1)
            k_transp<<<dim3(4, 16, BT), dim3(32, 8)>>>(1);   // refresh hT for next agg
        k_gfs_mma<<<dim3(4, Bb, KSPL), 128, SMEM_PIPE>>>(l + 1);
        k_gfs_red<<<(Bb * Vv * Cc + 255) / 256, 256>>>(fs_fc_b + l * Cc);
        k_gfs_glu<<<Bb * 64, 128>>>(l + 1, fs_glu_w + (size_t)l * 2 * Cc * Cc,
                                    fs_glu_b + l * 2 * Cc);
    }

    // head
    k_headg_mma<<<dim3(8, 32), 128, SMEM_PIPE>>>(glu_b);
    k_out_part<<<dim3(Bb, QSPL), 512>>>(out_w);
    k_out_red<<<(Bb * PP * Vv + 255) / 256, 256>>>(out_b, out);
}